// round 13
// baseline (speedup 1.0000x reference)
#include <cuda_runtime.h>
#include <cuda_fp16.h>
#include <math.h>
#include <stdint.h>

#define Zd  128
#define Nd  256
#define Fd  2048
#define Bd  8192
#define OSTRIDE 129   // Z+1

#define TMr 32        // batch rows per row-block
#define BF  64        // f tile
#define NT  (Fd / BF) // 32 tiles
#define NTC_GRID 128  // k_tc CTAs (each does 2 row-blocks)
#define RB   2
#define CNT_FULL 1024 // wproj blocks per tile

// ---------------- device scratch ----------------
__device__ float g_h1[4][Nd];
__device__ float g_bias[Fd];
__device__ float g_gate[Fd];
__device__ float g_sprod[Fd * Zd];    // win*wout per (f,z), fp32, deterministic
__device__ int   g_cnt[NT];           // tile readiness counters
__device__ __align__(16) uint16_t g_win_h16[Fd * Zd];   // [f][z]  fp16(w_in)
__device__ __align__(16) uint16_t g_woT_h16[Zd * Fd];   // [z][f]  fp16(w_out^T)

// ---------------- smem word layout (strides ≡ 4 mod 32, rows 16B-aligned) ----------------
#define STZ 68
#define STG 36
#define O_ZHI   0
#define O_ZLO   (O_ZHI  + TMr * STZ)      // 2176
#define O_WIH   (O_ZLO  + TMr * STZ)      // 4352
#define O_WOTH  (O_WIH  + BF * STZ)       // 8704
#define O_GHI   (O_WOTH + Zd * STG)       // 13312
#define O_GLO   (O_GHI  + TMr * STG)      // 14464
#define O_SPART (O_GLO  + TMr * STG)      // 15616
#define O_GS    (O_SPART + 256)           // 15872
#define O_TRS   (O_GS   + 64)             // 15936
#define SMEMW   (O_TRS  + TMr * 4)        // 16064
#define SMEM_TC (SMEMW * 4)               // 64256 B

// ---------------- helpers ----------------
__device__ __forceinline__ uint32_t smem_u32(const void* p) {
    uint32_t a;
    asm("{ .reg .u64 t; cvta.to.shared.u64 t, %1; cvt.u32.u64 %0, t; }" : "=r"(a) : "l"(p));
    return a;
}
__device__ __forceinline__ void ldsm_x4(uint32_t* r, uint32_t addr) {
    asm volatile("ldmatrix.sync.aligned.m8n8.x4.shared.b16 {%0,%1,%2,%3}, [%4];"
                 : "=r"(r[0]), "=r"(r[1]), "=r"(r[2]), "=r"(r[3]) : "r"(addr));
}
__device__ __forceinline__ uint32_t pack_split_f16(float a, float b, uint32_t& lopack) {
    __half ah = __float2half_rn(a);
    __half bh = __float2half_rn(b);
    __half al = __float2half_rn(a - __half2float(ah));
    __half bl = __float2half_rn(b - __half2float(bh));
    lopack = (uint32_t)__half_as_ushort(al) | ((uint32_t)__half_as_ushort(bl) << 16);
    return (uint32_t)__half_as_ushort(ah) | ((uint32_t)__half_as_ushort(bh) << 16);
}
__device__ __forceinline__ float fast_tanh(float x) {
    float ax = fabsf(x);
    float e;
    asm("ex2.approx.f32 %0, %1;" : "=f"(e) : "f"(ax * 2.8853900817779268f));
    float r;
    asm("rcp.approx.f32 %0, %1;" : "=f"(r) : "f"(e + 1.0f));
    return copysignf(1.0f - 2.0f * r, x);
}
__device__ __forceinline__ void mma_f16(float* c, const uint32_t* a, const uint32_t* b) {
    asm volatile(
        "mma.sync.aligned.m16n8k16.row.col.f32.f16.f16.f32 "
        "{%0,%1,%2,%3}, {%4,%5,%6,%7}, {%8,%9}, {%0,%1,%2,%3};"
        : "+f"(c[0]), "+f"(c[1]), "+f"(c[2]), "+f"(c[3])
        : "r"(a[0]), "r"(a[1]), "r"(a[2]), "r"(a[3]), "r"(b[0]), "r"(b[1]));
}

// ---------------- kernel 1: hypernet h0 -> h1 (32 blocks) + counter reset ----------------
__global__ void k_h1(const float* __restrict__ tt,
                     const float* __restrict__ W1, const float* __restrict__ B1,
                     const float* __restrict__ W2, const float* __restrict__ B2) {
    __shared__ float h0[Nd];
    const int k   = blockIdx.x >> 3;
    const int blk = blockIdx.x & 7;
    const int t   = threadIdx.x;
    if (blockIdx.x == 0 && t < NT) g_cnt[t] = 0;
    const float ts = tt[0];
    h0[t] = tanhf(fmaf(W1[k * Nd + t], ts, B1[k * Nd + t]));
    __syncthreads();

    const int wid  = t >> 5;
    const int lane = t & 31;
    const float4* h4 = (const float4*)h0;
#pragma unroll
    for (int r = 0; r < 4; r++) {
        const int n = blk * 32 + wid * 4 + r;
        const float4* w2 = (const float4*)(W2 + ((size_t)k * Nd + n) * Nd);
        float acc = 0.f;
#pragma unroll
        for (int i = 0; i < 2; i++) {
            float4 v = w2[lane + i * 32];
            float4 h = h4[lane + i * 32];
            acc = fmaf(v.x, h.x, fmaf(v.y, h.y, fmaf(v.z, h.z, fmaf(v.w, h.w, acc))));
        }
#pragma unroll
        for (int o = 16; o > 0; o >>= 1) acc += __shfl_xor_sync(0xFFFFFFFFu, acc, o);
        if (lane == 0) g_h1[k][n] = tanhf(acc + B2[k * Nd + n]);
    }
}

// ---------------- k_bg: bias & gate (independent of wproj) ----------------
__global__ void k_bg(const float* __restrict__ W3_b,    const float* __restrict__ b3_b,
                     const float* __restrict__ W3_gate, const float* __restrict__ b3_gate) {
    __shared__ float h2[Nd], h3[Nd];
    const int t = threadIdx.x;
    h2[t] = g_h1[2][t];  h2[t + 128] = g_h1[2][t + 128];
    h3[t] = g_h1[3][t];  h3[t + 128] = g_h1[3][t + 128];
    __syncthreads();

    const int wid  = t >> 5;
    const int lane = t & 31;
    const int f = blockIdx.x * 4 + wid;

    const float4* rb = (const float4*)(W3_b    + (size_t)f * Nd);
    const float4* rg = (const float4*)(W3_gate + (size_t)f * Nd);
    const float4* h2v = (const float4*)h2;
    const float4* h3v = (const float4*)h3;

    float accb = 0.f, accg = 0.f;
#pragma unroll
    for (int i = 0; i < 2; i++) {
        float4 v = rb[lane + i * 32], h = h2v[lane + i * 32];
        accb = fmaf(v.x, h.x, fmaf(v.y, h.y, fmaf(v.z, h.z, fmaf(v.w, h.w, accb))));
        float4 v2 = rg[lane + i * 32], h4 = h3v[lane + i * 32];
        accg = fmaf(v2.x, h4.x, fmaf(v2.y, h4.y, fmaf(v2.z, h4.z, fmaf(v2.w, h4.w, accg))));
    }
#pragma unroll
    for (int o = 16; o > 0; o >>= 1) {
        accb += __shfl_xor_sync(0xFFFFFFFFu, accb, o);
        accg += __shfl_xor_sync(0xFFFFFFFFu, accg, o);
    }
    if (lane == 0) {
        g_bias[f] = accb + b3_b[f];
        g_gate[f] = 1.f / (1.f + expf(-(accg + b3_gate[f])));
    }
}

// ---------------- k_wproj2: warp computes BOTH win & wout for one (f,z) ----------------
// f-major task order -> tiles complete in order; fp16 stored directly; signals g_cnt.
__global__ void k_wproj2(const float* __restrict__ W3_win,  const float* __restrict__ b3_win,
                         const float* __restrict__ W3_wout, const float* __restrict__ b3_wout) {
    __shared__ float h1a[Nd], h1b[Nd];
    const int t = threadIdx.x;
    h1a[t] = g_h1[0][t];
    h1b[t] = g_h1[1][t];
    __syncthreads();

    const int wid  = t >> 5;
    const int lane = t & 31;
    const int rid  = blockIdx.x * 8 + wid;   // 0 .. Fd*Zd-1
    const int f = rid >> 7;
    const int z = rid & 127;
    const size_t roff = (size_t)rid * Nd;

    const float4* __restrict__ ri = (const float4*)(W3_win + roff);
    const float4* __restrict__ ro = (const float4*)(W3_wout + roff);
    const float4* __restrict__ ha = (const float4*)h1a;
    const float4* __restrict__ hb = (const float4*)h1b;

    float ai = 0.f, ao = 0.f;
#pragma unroll
    for (int i = 0; i < 2; i++) {
        float4 v = ri[lane + i * 32], h = ha[lane + i * 32];
        ai = fmaf(v.x, h.x, fmaf(v.y, h.y, fmaf(v.z, h.z, fmaf(v.w, h.w, ai))));
        float4 v2 = ro[lane + i * 32], h2 = hb[lane + i * 32];
        ao = fmaf(v2.x, h2.x, fmaf(v2.y, h2.y, fmaf(v2.z, h2.z, fmaf(v2.w, h2.w, ao))));
    }
#pragma unroll
    for (int o = 16; o > 0; o >>= 1) {
        ai += __shfl_xor_sync(0xFFFFFFFFu, ai, o);
        ao += __shfl_xor_sync(0xFFFFFFFFu, ao, o);
    }
    if (lane == 0) {
        float win = ai + b3_win[rid];
        float wou = ao + b3_wout[rid];
        g_win_h16[rid] = __half_as_ushort(__float2half_rn(win));
        g_woT_h16[(size_t)z * Fd + f] = __half_as_ushort(__float2half_rn(wou));
        g_sprod[rid] = win * wou;
        __threadfence();
    }
    __syncthreads();
    if (t == 0) atomicAdd(&g_cnt[blockIdx.x >> 10], 1);
}

// ---------------- k_tc: fp16 split-activation double GEMM, tile-synchronized ----------------
__global__ __launch_bounds__(256)
void k_tc(const float* __restrict__ zlp, float* __restrict__ out) {
    extern __shared__ uint32_t smw[];
    float* smf = (float*)smw;
    const uint32_t sb = smem_u32(smw);

    const int t    = threadIdx.x;
    const int lane = t & 31;
    const int wid  = t >> 5;
    const int g    = lane >> 2;
    const int tq   = lane & 3;
    const int wr   = wid >> 2;       // 0..1
    const int wc   = wid & 3;        // 0..3

    const int rowA  = lane & 15;
    const int aofs  = ((lane >> 4) & 1) * 16;
    const int rowB  = (lane & 7) + ((lane >> 4) & 1) * 8;
    const int bofs  = ((lane >> 3) & 1) * 16;

    const uint32_t aZH = sb + O_ZHI * 4 + (wr * 16 + rowA) * (STZ * 4) + aofs;
    const uint32_t aZL = sb + O_ZLO * 4 + (wr * 16 + rowA) * (STZ * 4) + aofs;
    const uint32_t bWH = sb + O_WIH * 4 + (wc * 16 + rowB) * (STZ * 4) + bofs;
    const uint32_t aGH = sb + O_GHI * 4 + (wr * 16 + rowA) * (STG * 4) + aofs;
    const uint32_t aGL = sb + O_GLO * 4 + (wr * 16 + rowA) * (STG * 4) + aofs;
    const uint32_t bOH0 = sb + O_WOTH * 4 + (wc * 32 + rowB) * (STG * 4) + bofs;
    const uint32_t bOH1 = bOH0 + 16 * (STG * 4);

    const float invF = 1.0f / (float)Fd;

#pragma unroll 1
    for (int rb = 0; rb < RB; rb++) {
        const int b0 = (blockIdx.x + rb * NTC_GRID) * TMr;
        __syncthreads();   // protect smem reuse across rb passes

        // ---- stage z (hi/lo fp16) for this row-block ----
#pragma unroll
        for (int it = 0; it < 8; it++) {
            int idx = t + it * 256;
            int m = idx >> 6, kp = idx & 63;
            const float* zr = zlp + (size_t)(b0 + m) * OSTRIDE + 2 * kp;
            uint32_t lo, hi = pack_split_f16(zr[0], zr[1], lo);
            smw[O_ZHI + m * STZ + kp] = hi;
            smw[O_ZLO + m * STZ + kp] = lo;
        }

        float dz[4][4];
#pragma unroll
        for (int j = 0; j < 4; j++)
#pragma unroll
            for (int q = 0; q < 4; q++) dz[j][q] = 0.f;
        float tracc[2] = {0.f, 0.f};

#pragma unroll 1
        for (int tile = 0; tile < NT; tile++) {
            const int f0 = tile * BF;

            // ---- wait for tile's weights (producer: k_wproj2) ----
            if (t == 0) {
                volatile int* cp = g_cnt + tile;
                while (*cp < CNT_FULL) __nanosleep(64);
                __threadfence();
            }
            __syncthreads();   // syncA: weights ready; prev GEMM2 done with smem

            // ---- stage w_in tile (fp16) ----
#pragma unroll
            for (int it = 0; it < 4; it++) {
                int idx = t + it * 256;
                int fi = idx >> 4, seg = idx & 15;
                *(uint4*)&smw[O_WIH + fi * STZ + seg * 4] =
                    *(const uint4*)(g_win_h16 + (size_t)(f0 + fi) * Zd + seg * 8);
            }
            // ---- stage w_outT tile (fp16) ----
#pragma unroll
            for (int it = 0; it < 4; it++) {
                int idx = t + it * 256;
                int z = idx >> 3, seg = idx & 7;
                *(uint4*)&smw[O_WOTH + z * STG + seg * 4] =
                    *(const uint4*)(g_woT_h16 + (size_t)z * Fd + f0 + seg * 8);
            }
            // ---- s partials: thread t sums 32 z of f0+(t&63) ----
            {
                int f_loc = t & 63, zg = t >> 6;
                const float4* sp = (const float4*)(g_sprod + (size_t)(f0 + f_loc) * Zd + zg * 32);
                float acc = 0.f;
#pragma unroll
                for (int j = 0; j < 8; j++) {
                    float4 v = sp[j];
                    acc += (v.x + v.y) + (v.z + v.w);
                }
                smf[O_SPART + t] = acc;
            }
            __syncthreads();   // syncB

            // finalize gs = gate * s  (t<64), in parallel with GEMM1 below
            if (t < 64) {
                float s = (smf[O_SPART + t] + smf[O_SPART + t + 64])
                        + (smf[O_SPART + t + 128] + smf[O_SPART + t + 192]);
                smf[O_GS + t] = s * g_gate[f0 + t];
            }

            // ---- GEMM1: c1 = (zh+zl) @ wh^T ----
            float c1[2][4];
#pragma unroll
            for (int j = 0; j < 2; j++)
#pragma unroll
                for (int q = 0; q < 4; q++) c1[j][q] = 0.f;

#pragma unroll
            for (int kk = 0; kk < 8; kk++) {
                uint32_t ah[4], al[4], bh[4];
                ldsm_x4(ah, aZH + kk * 32);
                ldsm_x4(al, aZL + kk * 32);
                ldsm_x4(bh, bWH + kk * 32);
#pragma unroll
                for (int j = 0; j < 2; j++) {
                    mma_f16(c1[j], ah, bh + 2 * j);
                    mma_f16(c1[j], al, bh + 2 * j);
                }
            }
            __syncthreads();   // syncC: gs visible; all past GEMM1

            // ---- epilogue: tanh/gate/trace, stage g (hi/lo fp16) ----
#pragma unroll
            for (int j = 0; j < 2; j++) {
                const int fl = wc * 16 + j * 8 + 2 * tq;
                const int fc = f0 + fl;
                const float2 bi = __ldg((const float2*)(g_bias + fc));
                const float2 ga = __ldg((const float2*)(g_gate + fc));
                const float gsx = smf[O_GS + fl];
                const float gsy = smf[O_GS + fl + 1];
                const int r  = wr * 16 + g;
                const int cw = wc * 8 + j * 4 + tq;
                {
                    float h0 = fast_tanh(c1[j][0] + bi.x);
                    float h1 = fast_tanh(c1[j][1] + bi.y);
                    tracc[0] += (1.f - h0 * h0) * gsx + (1.f - h1 * h1) * gsy;
                    uint32_t lo, hi = pack_split_f16(h0 * ga.x, h1 * ga.y, lo);
                    smw[O_GHI + r * STG + cw] = hi;
                    smw[O_GLO + r * STG + cw] = lo;
                }
                {
                    float h2 = fast_tanh(c1[j][2] + bi.x);
                    float h3 = fast_tanh(c1[j][3] + bi.y);
                    tracc[1] += (1.f - h2 * h2) * gsx + (1.f - h3 * h3) * gsy;
                    uint32_t lo, hi = pack_split_f16(h2 * ga.x, h3 * ga.y, lo);
                    smw[O_GHI + (r + 8) * STG + cw] = hi;
                    smw[O_GLO + (r + 8) * STG + cw] = lo;
                }
            }
            __syncthreads();   // syncD

            // ---- GEMM2: dz += (gh+gl) @ wo_h ----
#pragma unroll
            for (int kk = 0; kk < 4; kk++) {
                uint32_t ah[4], al[4], bo_h[8];
                ldsm_x4(ah, aGH + kk * 32);
                ldsm_x4(al, aGL + kk * 32);
                ldsm_x4(bo_h,     bOH0 + kk * 32);
                ldsm_x4(bo_h + 4, bOH1 + kk * 32);
#pragma unroll
                for (int jn = 0; jn < 4; jn++) {
                    mma_f16(dz[jn], ah, bo_h + 2 * jn);
                    mma_f16(dz[jn], al, bo_h + 2 * jn);
                }
            }
        }

        // ---- write dz for this row-block ----
#pragma unroll
        for (int jn = 0; jn < 4; jn++) {
            const int r  = b0 + wr * 16 + g;
            const int z0 = wc * 32 + jn * 8 + 2 * tq;
            out[(size_t)r * OSTRIDE + z0]           = dz[jn][0] * invF;
            out[(size_t)r * OSTRIDE + z0 + 1]       = dz[jn][1] * invF;
            out[(size_t)(r + 8) * OSTRIDE + z0]     = dz[jn][2] * invF;
            out[(size_t)(r + 8) * OSTRIDE + z0 + 1] = dz[jn][3] * invF;
        }

        // ---- trace reduction for this row-block ----
        tracc[0] += __shfl_xor_sync(0xFFFFFFFFu, tracc[0], 1);
        tracc[0] += __shfl_xor_sync(0xFFFFFFFFu, tracc[0], 2);
        tracc[1] += __shfl_xor_sync(0xFFFFFFFFu, tracc[1], 1);
        tracc[1] += __shfl_xor_sync(0xFFFFFFFFu, tracc[1], 2);
        __syncthreads();
        if (tq == 0) {
            smf[O_TRS + (wr * 16 + g) * 4 + wc]     = tracc[0];
            smf[O_TRS + (wr * 16 + g + 8) * 4 + wc] = tracc[1];
        }
        __syncthreads();
        if (t < TMr) {
            float s = smf[O_TRS + t * 4 + 0] + smf[O_TRS + t * 4 + 1] +
                      smf[O_TRS + t * 4 + 2] + smf[O_TRS + t * 4 + 3];
            out[(size_t)(b0 + t) * OSTRIDE + Zd] = -s * invF;
        }
    }
}

// ---------------- launch: wproj (s0) overlapped with k_tc (s1) ----------------
extern "C" void kernel_launch(void* const* d_in, const int* in_sizes, int n_in,
                              void* d_out, int out_size) {
    const float* t       = (const float*)d_in[0];
    const float* zlp     = (const float*)d_in[1];
    const float* W1      = (const float*)d_in[2];
    const float* B1      = (const float*)d_in[3];
    const float* W2      = (const float*)d_in[4];
    const float* B2      = (const float*)d_in[5];
    const float* W3_win  = (const float*)d_in[6];
    const float* b3_win  = (const float*)d_in[7];
    const float* W3_wout = (const float*)d_in[8];
    const float* b3_wout = (const float*)d_in[9];
    const float* W3_b    = (const float*)d_in[10];
    const float* b3_b    = (const float*)d_in[11];
    const float* W3_gate = (const float*)d_in[12];
    const float* b3_gate = (const float*)d_in[13];
    float* out = (float*)d_out;

    cudaFuncSetAttribute(k_tc, cudaFuncAttributeMaxDynamicSharedMemorySize, SMEM_TC);

    int plo = 0, phi = 0;
    cudaDeviceGetStreamPriorityRange(&plo, &phi);
    cudaStream_t s1;
    cudaStreamCreateWithPriority(&s1, cudaStreamNonBlocking, phi);
    cudaEvent_t ev0, evj;
    cudaEventCreateWithFlags(&ev0, cudaEventDisableTiming);
    cudaEventCreateWithFlags(&evj, cudaEventDisableTiming);

    k_h1<<<32, 256>>>(t, W1, B1, W2, B2);          // also resets g_cnt
    k_bg<<<512, 128>>>(W3_b, b3_b, W3_gate, b3_gate);
    cudaEventRecord(ev0, 0);

    k_wproj2<<<Fd * Zd / 8, 256>>>(W3_win, b3_win, W3_wout, b3_wout);  // producer on s0

    cudaStreamWaitEvent(s1, ev0, 0);
    k_tc<<<NTC_GRID, 256, SMEM_TC, s1>>>(zlp, out);                    // consumer on s1

    cudaEventRecord(evj, s1);
    cudaStreamWaitEvent(0, evj, 0);
    // stream/events intentionally leaked: called only a handful of times
    // (correctness + capture); no device memory involved.
}

// round 14
// speedup vs baseline: 3.3748x; 3.3748x over previous
#include <cuda_runtime.h>
#include <cuda_fp16.h>
#include <math.h>
#include <stdint.h>

#define Zd  128
#define Nd  256
#define Fd  2048
#define Bd  8192
#define OSTRIDE 129   // Z+1

#define TMr 32        // batch rows per CTA
#define BF  64        // f tile
#define NT  (Fd / BF) // 32 tiles

// ---------------- device scratch ----------------
__device__ float g_h1[4][Nd];
__device__ float g_win  [Fd * Zd];
__device__ float g_wout [Fd * Zd];
__device__ float g_woutT[Zd * Fd];
__device__ float g_bias[Fd];
__device__ float g_gate[Fd];
__device__ float g_gs  [Fd];
// fp16 weights (made by k_split)
__device__ __align__(16) uint16_t g_win_h16[Fd * Zd];   // [f][z]  fp16(w_in)
__device__ __align__(16) uint16_t g_woT_h16[Zd * Fd];   // [z][f]  fp16(w_out^T)

// ---------------- smem word layout (strides ≡ 4 mod 32, rows 16B-aligned) ----------------
#define STZ 68   // 64 data words + 4 pad (272 B rows)
#define STG 36   // 32 data words + 4 pad (144 B rows)
#define WIBUF  (BF * STZ)     // 4352 words per w_in buffer
#define WOTBUF (Zd * STG)     // 4608 words per w_outT buffer
#define O_ZHI   0
#define O_ZLO   (O_ZHI  + TMr * STZ)      // 2176
#define O_WIH   (O_ZLO  + TMr * STZ)      // 4352  (2 buffers)
#define O_WOTH  (O_WIH  + 2 * WIBUF)      // 13056 (2 buffers)
#define O_GHI   (O_WOTH + 2 * WOTBUF)     // 22272
#define O_GLO   (O_GHI  + TMr * STG)      // 23424
#define O_TRS   (O_GLO  + TMr * STG)      // 24576
#define SMEMW   (O_TRS  + TMr * 4)        // 24704 words
#define SMEM_TC (SMEMW * 4)               // 98816 B -> 2 CTAs/SM

// ---------------- helpers ----------------
__device__ __forceinline__ uint32_t smem_u32(const void* p) {
    uint32_t a;
    asm("{ .reg .u64 t; cvta.to.shared.u64 t, %1; cvt.u32.u64 %0, t; }" : "=r"(a) : "l"(p));
    return a;
}
__device__ __forceinline__ void ldsm_x4(uint32_t* r, uint32_t addr) {
    asm volatile("ldmatrix.sync.aligned.m8n8.x4.shared.b16 {%0,%1,%2,%3}, [%4];"
                 : "=r"(r[0]), "=r"(r[1]), "=r"(r[2]), "=r"(r[3]) : "r"(addr));
}
#define CP_ASYNC16(dst, src) asm volatile("cp.async.cg.shared.global [%0], [%1], 16;" :: "r"(dst), "l"(src))
#define CP_COMMIT()          asm volatile("cp.async.commit_group;" ::: "memory")
#define CP_WAIT0()           asm volatile("cp.async.wait_group 0;" ::: "memory")

__device__ __forceinline__ uint32_t pack_split_f16(float a, float b, uint32_t& lopack) {
    __half ah = __float2half_rn(a);
    __half bh = __float2half_rn(b);
    __half al = __float2half_rn(a - __half2float(ah));
    __half bl = __float2half_rn(b - __half2float(bh));
    lopack = (uint32_t)__half_as_ushort(al) | ((uint32_t)__half_as_ushort(bl) << 16);
    return (uint32_t)__half_as_ushort(ah) | ((uint32_t)__half_as_ushort(bh) << 16);
}
__device__ __forceinline__ float fast_tanh(float x) {
    float ax = fabsf(x);
    float e;
    asm("ex2.approx.f32 %0, %1;" : "=f"(e) : "f"(ax * 2.8853900817779268f));
    float r;
    asm("rcp.approx.f32 %0, %1;" : "=f"(r) : "f"(e + 1.0f));
    return copysignf(1.0f - 2.0f * r, x);
}
__device__ __forceinline__ void mma_f16(float* c, const uint32_t* a, const uint32_t* b) {
    asm volatile(
        "mma.sync.aligned.m16n8k16.row.col.f32.f16.f16.f32 "
        "{%0,%1,%2,%3}, {%4,%5,%6,%7}, {%8,%9}, {%0,%1,%2,%3};"
        : "+f"(c[0]), "+f"(c[1]), "+f"(c[2]), "+f"(c[3])
        : "r"(a[0]), "r"(a[1]), "r"(a[2]), "r"(a[3]), "r"(b[0]), "r"(b[1]));
}

// ---------------- kernel 1: hypernet h0 -> h1 (32 blocks) ----------------
__global__ void k_h1(const float* __restrict__ tt,
                     const float* __restrict__ W1, const float* __restrict__ B1,
                     const float* __restrict__ W2, const float* __restrict__ B2) {
    __shared__ float h0[Nd];
    const int k   = blockIdx.x >> 3;
    const int blk = blockIdx.x & 7;
    const int t   = threadIdx.x;
    const float ts = tt[0];
    h0[t] = tanhf(fmaf(W1[k * Nd + t], ts, B1[k * Nd + t]));
    __syncthreads();

    const int wid  = t >> 5;
    const int lane = t & 31;
    const float4* h4 = (const float4*)h0;
#pragma unroll
    for (int r = 0; r < 4; r++) {
        const int n = blk * 32 + wid * 4 + r;
        const float4* w2 = (const float4*)(W2 + ((size_t)k * Nd + n) * Nd);
        float acc = 0.f;
#pragma unroll
        for (int i = 0; i < 2; i++) {
            float4 v = w2[lane + i * 32];
            float4 h = h4[lane + i * 32];
            acc = fmaf(v.x, h.x, fmaf(v.y, h.y, fmaf(v.z, h.z, fmaf(v.w, h.w, acc))));
        }
#pragma unroll
        for (int o = 16; o > 0; o >>= 1) acc += __shfl_xor_sync(0xFFFFFFFFu, acc, o);
        if (lane == 0) g_h1[k][n] = tanhf(acc + B2[k * Nd + n]);
    }
}

// ---------------- kernel 2: w_in / w_out matvecs ----------------
__global__ void k_wproj(const float* __restrict__ W3_win,  const float* __restrict__ b3_win,
                        const float* __restrict__ W3_wout, const float* __restrict__ b3_wout) {
    __shared__ float h1a[Nd], h1b[Nd];
    const int t = threadIdx.x;
    h1a[t] = g_h1[0][t];
    h1b[t] = g_h1[1][t];
    __syncthreads();

    const int wid  = t >> 5;
    const int lane = t & 31;
    long r = (long)blockIdx.x * 8 + wid;

    const float* wmat; const float* bias; const float* hv; long rr; int isOut;
    if (r < (long)Fd * Zd) { rr = r;                 wmat = W3_win;  bias = b3_win;  hv = h1a; isOut = 0; }
    else                   { rr = r - (long)Fd * Zd; wmat = W3_wout; bias = b3_wout; hv = h1b; isOut = 1; }

    const float4* __restrict__ row = (const float4*)(wmat + rr * Nd);
    const float4* __restrict__ hv4 = (const float4*)hv;
    float acc = 0.f;
#pragma unroll
    for (int i = 0; i < 2; i++) {
        float4 v = row[lane + i * 32];
        float4 h = hv4[lane + i * 32];
        acc = fmaf(v.x, h.x, acc);
        acc = fmaf(v.y, h.y, acc);
        acc = fmaf(v.z, h.z, acc);
        acc = fmaf(v.w, h.w, acc);
    }
#pragma unroll
    for (int o = 16; o > 0; o >>= 1) acc += __shfl_xor_sync(0xFFFFFFFFu, acc, o);
    if (lane == 0) {
        float v = acc + bias[rr];
        if (isOut) {
            g_wout[rr] = v;
            int f = (int)(rr >> 7);
            int z = (int)(rr & 127);
            g_woutT[(size_t)z * Fd + f] = v;
        } else {
            g_win[rr] = v;
        }
    }
}

// ---------------- k_split: fp16 weight conversion ----------------
__global__ void k_split() {
    int idx = blockIdx.x * 256 + threadIdx.x;
    g_win_h16[idx] = __half_as_ushort(__float2half_rn(g_win[idx]));
    g_woT_h16[idx] = __half_as_ushort(__float2half_rn(g_woutT[idx]));
}

// ---------------- kernel 3: bias, gate, gate*s ----------------
__global__ void k_small(const float* __restrict__ W3_b,    const float* __restrict__ b3_b,
                        const float* __restrict__ W3_gate, const float* __restrict__ b3_gate) {
    __shared__ float h2[Nd], h3[Nd];
    const int t = threadIdx.x;
    h2[t] = g_h1[2][t];  h2[t + 128] = g_h1[2][t + 128];
    h3[t] = g_h1[3][t];  h3[t + 128] = g_h1[3][t + 128];
    __syncthreads();

    const int wid  = t >> 5;
    const int lane = t & 31;
    const int f = blockIdx.x * 4 + wid;

    const float4* rb = (const float4*)(W3_b    + (size_t)f * Nd);
    const float4* rg = (const float4*)(W3_gate + (size_t)f * Nd);
    const float4* h2v = (const float4*)h2;
    const float4* h3v = (const float4*)h3;

    float accb = 0.f, accg = 0.f;
#pragma unroll
    for (int i = 0; i < 2; i++) {
        float4 v = rb[lane + i * 32], h = h2v[lane + i * 32];
        accb = fmaf(v.x, h.x, fmaf(v.y, h.y, fmaf(v.z, h.z, fmaf(v.w, h.w, accb))));
        float4 v2 = rg[lane + i * 32], h4 = h3v[lane + i * 32];
        accg = fmaf(v2.x, h4.x, fmaf(v2.y, h4.y, fmaf(v2.z, h4.z, fmaf(v2.w, h4.w, accg))));
    }
    const float4 a  = ((const float4*)(g_win  + (size_t)f * Zd))[lane];
    const float4 b4 = ((const float4*)(g_wout + (size_t)f * Zd))[lane];
    float accs = a.x * b4.x + a.y * b4.y + a.z * b4.z + a.w * b4.w;

#pragma unroll
    for (int o = 16; o > 0; o >>= 1) {
        accb += __shfl_xor_sync(0xFFFFFFFFu, accb, o);
        accg += __shfl_xor_sync(0xFFFFFFFFu, accg, o);
        accs += __shfl_xor_sync(0xFFFFFFFFu, accs, o);
    }
    if (lane == 0) {
        g_bias[f] = accb + b3_b[f];
        float gt = 1.f / (1.f + expf(-(accg + b3_gate[f])));
        g_gate[f] = gt;
        g_gs[f]   = gt * accs;
    }
}

// ---------------- weight tile prefetch (cp.async, 8 x 16B per thread) ----------------
__device__ __forceinline__ void prefetch_w(uint32_t sb, int buf, int f0, int t) {
#pragma unroll
    for (int it = 0; it < 4; it++) {
        int idx = t + it * 256;            // 0..1023
        int fi = idx >> 4, seg = idx & 15;
        uint32_t dst = sb + (uint32_t)(O_WIH + buf * WIBUF + fi * STZ + seg * 4) * 4u;
        CP_ASYNC16(dst, g_win_h16 + (size_t)(f0 + fi) * Zd + seg * 8);
    }
#pragma unroll
    for (int it = 0; it < 4; it++) {
        int idx = t + it * 256;            // 0..1023
        int z = idx >> 3, seg = idx & 7;
        uint32_t dst = sb + (uint32_t)(O_WOTH + buf * WOTBUF + z * STG + seg * 4) * 4u;
        CP_ASYNC16(dst, g_woT_h16 + (size_t)z * Fd + f0 + seg * 8);
    }
}

// ---------------- k_tc: fp16 split-activation double GEMM, double-buffered ----------------
__global__ __launch_bounds__(256, 2)
void k_tc(const float* __restrict__ zlp, float* __restrict__ out) {
    extern __shared__ uint32_t smw[];
    float* smf = (float*)smw;
    const uint32_t sb = smem_u32(smw);

    const int t    = threadIdx.x;
    const int lane = t & 31;
    const int wid  = t >> 5;
    const int g    = lane >> 2;
    const int tq   = lane & 3;
    const int wr   = wid >> 2;       // 0..1
    const int wc   = wid & 3;        // 0..3
    const int b0   = blockIdx.x * TMr;

    const int rowA  = lane & 15;
    const int aofs  = ((lane >> 4) & 1) * 16;
    const int rowB  = (lane & 7) + ((lane >> 4) & 1) * 8;
    const int bofs  = ((lane >> 3) & 1) * 16;

    const uint32_t aZH = sb + O_ZHI * 4 + (wr * 16 + rowA) * (STZ * 4) + aofs;
    const uint32_t aZL = sb + O_ZLO * 4 + (wr * 16 + rowA) * (STZ * 4) + aofs;
    const uint32_t bWHb = sb + O_WIH * 4 + (wc * 16 + rowB) * (STZ * 4) + bofs;
    const uint32_t aGH = sb + O_GHI * 4 + (wr * 16 + rowA) * (STG * 4) + aofs;
    const uint32_t aGL = sb + O_GLO * 4 + (wr * 16 + rowA) * (STG * 4) + aofs;
    const uint32_t bOHb = sb + O_WOTH * 4 + (wc * 32 + rowB) * (STG * 4) + bofs;

    // prefetch tile 0 into buf 0, overlapping z staging
    prefetch_w(sb, 0, 0, t);
    CP_COMMIT();

    // ---- stage z (hi/lo fp16), once ----
#pragma unroll
    for (int it = 0; it < 8; it++) {
        int idx = t + it * 256;
        int m = idx >> 6, kp = idx & 63;
        const float* zr = zlp + (size_t)(b0 + m) * OSTRIDE + 2 * kp;
        uint32_t lo, hi = pack_split_f16(zr[0], zr[1], lo);
        smw[O_ZHI + m * STZ + kp] = hi;
        smw[O_ZLO + m * STZ + kp] = lo;
    }

    float dz[4][4];
#pragma unroll
    for (int j = 0; j < 4; j++)
#pragma unroll
        for (int q = 0; q < 4; q++) dz[j][q] = 0.f;
    float tracc[2] = {0.f, 0.f};

    CP_WAIT0();
    __syncthreads();

#pragma unroll 1
    for (int tile = 0; tile < NT; tile++) {
        const int f0 = tile * BF;
        const int buf = tile & 1;
        const uint32_t bWH  = bWHb + (uint32_t)(buf * WIBUF) * 4u;
        const uint32_t bOH0 = bOHb + (uint32_t)(buf * WOTBUF) * 4u;
        const uint32_t bOH1 = bOH0 + 16 * (STG * 4);

        // fire prefetch of next tile into the other buffer (safe: that buffer's
        // last reader was GEMM2 of tile-1, sealed by the end-of-iteration sync)
        if (tile + 1 < NT) {
            prefetch_w(sb, buf ^ 1, f0 + BF, t);
            CP_COMMIT();
        }

        // ---- GEMM1: c1 = (zh+zl) @ wh^T  (32x64; warp tile 16m x 16f) ----
        float c1[2][4];
#pragma unroll
        for (int j = 0; j < 2; j++)
#pragma unroll
            for (int q = 0; q < 4; q++) c1[j][q] = 0.f;

#pragma unroll
        for (int kk = 0; kk < 8; kk++) {
            uint32_t ah[4], al[4], bh[4];
            ldsm_x4(ah, aZH + kk * 32);
            ldsm_x4(al, aZL + kk * 32);
            ldsm_x4(bh, bWH + kk * 32);
#pragma unroll
            for (int j = 0; j < 2; j++) {
                mma_f16(c1[j], ah, bh + 2 * j);
                mma_f16(c1[j], al, bh + 2 * j);
            }
        }

        // ---- epilogue: tanh/gate/trace, stage g (hi/lo fp16) ----
#pragma unroll
        for (int j = 0; j < 2; j++) {
            const int fc = f0 + wc * 16 + j * 8 + 2 * tq;
            const float2 bi = __ldg((const float2*)(g_bias + fc));
            const float2 ga = __ldg((const float2*)(g_gate + fc));
            const float2 gs = __ldg((const float2*)(g_gs + fc));
            const int r  = wr * 16 + g;
            const int cw = wc * 8 + j * 4 + tq;
            {
                float h0 = fast_tanh(c1[j][0] + bi.x);
                float h1 = fast_tanh(c1[j][1] + bi.y);
                tracc[0] += (1.f - h0 * h0) * gs.x + (1.f - h1 * h1) * gs.y;
                uint32_t lo, hi = pack_split_f16(h0 * ga.x, h1 * ga.y, lo);
                smw[O_GHI + r * STG + cw] = hi;
                smw[O_GLO + r * STG + cw] = lo;
            }
            {
                float h2 = fast_tanh(c1[j][2] + bi.x);
                float h3 = fast_tanh(c1[j][3] + bi.y);
                tracc[1] += (1.f - h2 * h2) * gs.x + (1.f - h3 * h3) * gs.y;
                uint32_t lo, hi = pack_split_f16(h2 * ga.x, h3 * ga.y, lo);
                smw[O_GHI + (r + 8) * STG + cw] = hi;
                smw[O_GLO + (r + 8) * STG + cw] = lo;
            }
        }
        __syncthreads();   // g staged before GEMM2 reads it

        // ---- GEMM2: dz += (gh+gl) @ wo_h (32m x 128z; warp 16m x 32z, k=64) ----
#pragma unroll
        for (int kk = 0; kk < 4; kk++) {
            uint32_t ah[4], al[4], bo_h[8];
            ldsm_x4(ah, aGH + kk * 32);
            ldsm_x4(al, aGL + kk * 32);
            ldsm_x4(bo_h,     bOH0 + kk * 32);
            ldsm_x4(bo_h + 4, bOH1 + kk * 32);
#pragma unroll
            for (int jn = 0; jn < 4; jn++) {
                mma_f16(dz[jn], ah, bo_h + 2 * jn);
                mma_f16(dz[jn], al, bo_h + 2 * jn);
            }
        }

        // next tile's weights must have landed; also seals this buffer (g + weights)
        CP_WAIT0();
        __syncthreads();
    }

    // ---- write dz ----
    const float invF = 1.0f / (float)Fd;
#pragma unroll
    for (int jn = 0; jn < 4; jn++) {
        const int r  = b0 + wr * 16 + g;
        const int z0 = wc * 32 + jn * 8 + 2 * tq;
        out[(size_t)r * OSTRIDE + z0]           = dz[jn][0] * invF;
        out[(size_t)r * OSTRIDE + z0 + 1]       = dz[jn][1] * invF;
        out[(size_t)(r + 8) * OSTRIDE + z0]     = dz[jn][2] * invF;
        out[(size_t)(r + 8) * OSTRIDE + z0 + 1] = dz[jn][3] * invF;
    }

    // ---- trace reduction ----
    tracc[0] += __shfl_xor_sync(0xFFFFFFFFu, tracc[0], 1);
    tracc[0] += __shfl_xor_sync(0xFFFFFFFFu, tracc[0], 2);
    tracc[1] += __shfl_xor_sync(0xFFFFFFFFu, tracc[1], 1);
    tracc[1] += __shfl_xor_sync(0xFFFFFFFFu, tracc[1], 2);
    if (tq == 0) {
        smf[O_TRS + (wr * 16 + g) * 4 + wc]     = tracc[0];
        smf[O_TRS + (wr * 16 + g + 8) * 4 + wc] = tracc[1];
    }
    __syncthreads();
    if (t < TMr) {
        float s = smf[O_TRS + t * 4 + 0] + smf[O_TRS + t * 4 + 1] +
                  smf[O_TRS + t * 4 + 2] + smf[O_TRS + t * 4 + 3];
        out[(size_t)(b0 + t) * OSTRIDE + Zd] = -s * invF;
    }
}

// ---------------- launch ----------------
extern "C" void kernel_launch(void* const* d_in, const int* in_sizes, int n_in,
                              void* d_out, int out_size) {
    const float* t       = (const float*)d_in[0];
    const float* zlp     = (const float*)d_in[1];
    const float* W1      = (const float*)d_in[2];
    const float* B1      = (const float*)d_in[3];
    const float* W2      = (const float*)d_in[4];
    const float* B2      = (const float*)d_in[5];
    const float* W3_win  = (const float*)d_in[6];
    const float* b3_win  = (const float*)d_in[7];
    const float* W3_wout = (const float*)d_in[8];
    const float* b3_wout = (const float*)d_in[9];
    const float* W3_b    = (const float*)d_in[10];
    const float* b3_b    = (const float*)d_in[11];
    const float* W3_gate = (const float*)d_in[12];
    const float* b3_gate = (const float*)d_in[13];
    float* out = (float*)d_out;

    cudaFuncSetAttribute(k_tc, cudaFuncAttributeMaxDynamicSharedMemorySize, SMEM_TC);

    k_h1   <<<32,    256>>>(t, W1, B1, W2, B2);
    k_wproj<<<65536, 256>>>(W3_win, b3_win, W3_wout, b3_wout);
    k_split<<<Fd * Zd / 256, 256>>>();
    k_small<<<512,   128>>>(W3_b, b3_b, W3_gate, b3_gate);
    k_tc   <<<Bd / TMr, 256, SMEM_TC>>>(zlp, out);
}

// round 15
// speedup vs baseline: 3.8232x; 1.1328x over previous
#include <cuda_runtime.h>
#include <cuda_fp16.h>
#include <math.h>
#include <stdint.h>

#define Zd  128
#define Nd  256
#define Fd  2048
#define Bd  8192
#define OSTRIDE 129   // Z+1

#define TMr 32        // batch rows per CTA
#define BF  64        // f tile
#define NT  (Fd / BF) // 32 tiles

// ---------------- device scratch ----------------
__device__ float g_h1[4][Nd];
__device__ float g_win  [Fd * Zd];
__device__ float g_wout [Fd * Zd];
__device__ float g_bias[Fd];
__device__ float g_gate[Fd];
__device__ float g_gs  [Fd];
// fp16 weights (made directly by k_wproj)
__device__ __align__(16) uint16_t g_win_h16[Fd * Zd];   // [f][z]  fp16(w_in)
__device__ __align__(16) uint16_t g_woT_h16[Zd * Fd];   // [z][f]  fp16(w_out^T)

// ---------------- smem word layout (strides ≡ 4 mod 32, rows 16B-aligned) ----------------
#define STZ 68   // 64 data words + 4 pad (272 B rows)
#define STG 36   // 32 data words + 4 pad (144 B rows)
#define WIBUF  (BF * STZ)     // 4352 words per w_in buffer
#define WOTBUF (Zd * STG)     // 4608 words per w_outT buffer
#define O_ZHI   0
#define O_WIH   (O_ZHI  + TMr * STZ)      // 2176  (2 buffers)
#define O_WOTH  (O_WIH  + 2 * WIBUF)      // 10880 (2 buffers)
#define O_GHI   (O_WOTH + 2 * WOTBUF)     // 20096
#define O_TRS   (O_GHI  + TMr * STG)      // 21248
#define SMEMW   (O_TRS  + TMr * 4)        // 21376 words
#define SMEM_TC (SMEMW * 4)               // 85504 B -> 2 CTAs/SM

// ---------------- helpers ----------------
__device__ __forceinline__ uint32_t smem_u32(const void* p) {
    uint32_t a;
    asm("{ .reg .u64 t; cvta.to.shared.u64 t, %1; cvt.u32.u64 %0, t; }" : "=r"(a) : "l"(p));
    return a;
}
__device__ __forceinline__ void ldsm_x4(uint32_t* r, uint32_t addr) {
    asm volatile("ldmatrix.sync.aligned.m8n8.x4.shared.b16 {%0,%1,%2,%3}, [%4];"
                 : "=r"(r[0]), "=r"(r[1]), "=r"(r[2]), "=r"(r[3]) : "r"(addr));
}
#define CP_ASYNC16(dst, src) asm volatile("cp.async.cg.shared.global [%0], [%1], 16;" :: "r"(dst), "l"(src))
#define CP_COMMIT()          asm volatile("cp.async.commit_group;" ::: "memory")
#define CP_WAIT0()           asm volatile("cp.async.wait_group 0;" ::: "memory")

__device__ __forceinline__ uint32_t pack_f16x2(float a, float b) {
    __half2 h = __floats2half2_rn(a, b);
    return *(uint32_t*)&h;
}
__device__ __forceinline__ float fast_tanh(float x) {
    float ax = fabsf(x);
    float e;
    asm("ex2.approx.f32 %0, %1;" : "=f"(e) : "f"(ax * 2.8853900817779268f));
    float r;
    asm("rcp.approx.f32 %0, %1;" : "=f"(r) : "f"(e + 1.0f));
    return copysignf(1.0f - 2.0f * r, x);
}
__device__ __forceinline__ void mma_f16(float* c, const uint32_t* a, const uint32_t* b) {
    asm volatile(
        "mma.sync.aligned.m16n8k16.row.col.f32.f16.f16.f32 "
        "{%0,%1,%2,%3}, {%4,%5,%6,%7}, {%8,%9}, {%0,%1,%2,%3};"
        : "+f"(c[0]), "+f"(c[1]), "+f"(c[2]), "+f"(c[3])
        : "r"(a[0]), "r"(a[1]), "r"(a[2]), "r"(a[3]), "r"(b[0]), "r"(b[1]));
}

// ---------------- kernel 1: hypernet h0 -> h1 (32 blocks) ----------------
__global__ void k_h1(const float* __restrict__ tt,
                     const float* __restrict__ W1, const float* __restrict__ B1,
                     const float* __restrict__ W2, const float* __restrict__ B2) {
    __shared__ float h0[Nd];
    const int k   = blockIdx.x >> 3;
    const int blk = blockIdx.x & 7;
    const int t   = threadIdx.x;
    const float ts = tt[0];
    h0[t] = tanhf(fmaf(W1[k * Nd + t], ts, B1[k * Nd + t]));
    __syncthreads();

    const int wid  = t >> 5;
    const int lane = t & 31;
    const float4* h4 = (const float4*)h0;
#pragma unroll
    for (int r = 0; r < 4; r++) {
        const int n = blk * 32 + wid * 4 + r;
        const float4* w2 = (const float4*)(W2 + ((size_t)k * Nd + n) * Nd);
        float acc = 0.f;
#pragma unroll
        for (int i = 0; i < 2; i++) {
            float4 v = w2[lane + i * 32];
            float4 h = h4[lane + i * 32];
            acc = fmaf(v.x, h.x, fmaf(v.y, h.y, fmaf(v.z, h.z, fmaf(v.w, h.w, acc))));
        }
#pragma unroll
        for (int o = 16; o > 0; o >>= 1) acc += __shfl_xor_sync(0xFFFFFFFFu, acc, o);
        if (lane == 0) g_h1[k][n] = tanhf(acc + B2[k * Nd + n]);
    }
}

// ---------------- kernel 2: w_in / w_out matvecs (+ direct fp16 emit) ----------------
__global__ void k_wproj(const float* __restrict__ W3_win,  const float* __restrict__ b3_win,
                        const float* __restrict__ W3_wout, const float* __restrict__ b3_wout) {
    __shared__ float h1a[Nd], h1b[Nd];
    const int t = threadIdx.x;
    h1a[t] = g_h1[0][t];
    h1b[t] = g_h1[1][t];
    __syncthreads();

    const int wid  = t >> 5;
    const int lane = t & 31;
    long r = (long)blockIdx.x * 8 + wid;

    const float* wmat; const float* bias; const float* hv; long rr; int isOut;
    if (r < (long)Fd * Zd) { rr = r;                 wmat = W3_win;  bias = b3_win;  hv = h1a; isOut = 0; }
    else                   { rr = r - (long)Fd * Zd; wmat = W3_wout; bias = b3_wout; hv = h1b; isOut = 1; }

    const float4* __restrict__ row = (const float4*)(wmat + rr * Nd);
    const float4* __restrict__ hv4 = (const float4*)hv;
    float acc = 0.f;
#pragma unroll
    for (int i = 0; i < 2; i++) {
        float4 v = row[lane + i * 32];
        float4 h = hv4[lane + i * 32];
        acc = fmaf(v.x, h.x, acc);
        acc = fmaf(v.y, h.y, acc);
        acc = fmaf(v.z, h.z, acc);
        acc = fmaf(v.w, h.w, acc);
    }
#pragma unroll
    for (int o = 16; o > 0; o >>= 1) acc += __shfl_xor_sync(0xFFFFFFFFu, acc, o);
    if (lane == 0) {
        float v = acc + bias[rr];
        uint16_t v16 = __half_as_ushort(__float2half_rn(v));
        if (isOut) {
            g_wout[rr] = v;
            int f = (int)(rr >> 7);
            int z = (int)(rr & 127);
            g_woT_h16[(size_t)z * Fd + f] = v16;
        } else {
            g_win[rr] = v;
            g_win_h16[rr] = v16;
        }
    }
}

// ---------------- kernel 3: bias, gate, gate*s ----------------
__global__ void k_small(const float* __restrict__ W3_b,    const float* __restrict__ b3_b,
                        const float* __restrict__ W3_gate, const float* __restrict__ b3_gate) {
    __shared__ float h2[Nd], h3[Nd];
    const int t = threadIdx.x;
    h2[t] = g_h1[2][t];  h2[t + 128] = g_h1[2][t + 128];
    h3[t] = g_h1[3][t];  h3[t + 128] = g_h1[3][t + 128];
    __syncthreads();

    const int wid  = t >> 5;
    const int lane = t & 31;
    const int f = blockIdx.x * 4 + wid;

    const float4* rb = (const float4*)(W3_b    + (size_t)f * Nd);
    const float4* rg = (const float4*)(W3_gate + (size_t)f * Nd);
    const float4* h2v = (const float4*)h2;
    const float4* h3v = (const float4*)h3;

    float accb = 0.f, accg = 0.f;
#pragma unroll
    for (int i = 0; i < 2; i++) {
        float4 v = rb[lane + i * 32], h = h2v[lane + i * 32];
        accb = fmaf(v.x, h.x, fmaf(v.y, h.y, fmaf(v.z, h.z, fmaf(v.w, h.w, accb))));
        float4 v2 = rg[lane + i * 32], h4 = h3v[lane + i * 32];
        accg = fmaf(v2.x, h4.x, fmaf(v2.y, h4.y, fmaf(v2.z, h4.z, fmaf(v2.w, h4.w, accg))));
    }
    const float4 a  = ((const float4*)(g_win  + (size_t)f * Zd))[lane];
    const float4 b4 = ((const float4*)(g_wout + (size_t)f * Zd))[lane];
    float accs = a.x * b4.x + a.y * b4.y + a.z * b4.z + a.w * b4.w;

#pragma unroll
    for (int o = 16; o > 0; o >>= 1) {
        accb += __shfl_xor_sync(0xFFFFFFFFu, accb, o);
        accg += __shfl_xor_sync(0xFFFFFFFFu, accg, o);
        accs += __shfl_xor_sync(0xFFFFFFFFu, accs, o);
    }
    if (lane == 0) {
        g_bias[f] = accb + b3_b[f];
        float gt = 1.f / (1.f + expf(-(accg + b3_gate[f])));
        g_gate[f] = gt;
        g_gs[f]   = gt * accs;
    }
}

// ---------------- weight tile prefetch (cp.async, 8 x 16B per thread) ----------------
__device__ __forceinline__ void prefetch_w(uint32_t sb, int buf, int f0, int t) {
#pragma unroll
    for (int it = 0; it < 4; it++) {
        int idx = t + it * 256;            // 0..1023
        int fi = idx >> 4, seg = idx & 15;
        uint32_t dst = sb + (uint32_t)(O_WIH + buf * WIBUF + fi * STZ + seg * 4) * 4u;
        CP_ASYNC16(dst, g_win_h16 + (size_t)(f0 + fi) * Zd + seg * 8);
    }
#pragma unroll
    for (int it = 0; it < 4; it++) {
        int idx = t + it * 256;            // 0..1023
        int z = idx >> 3, seg = idx & 7;
        uint32_t dst = sb + (uint32_t)(O_WOTH + buf * WOTBUF + z * STG + seg * 4) * 4u;
        CP_ASYNC16(dst, g_woT_h16 + (size_t)z * Fd + f0 + seg * 8);
    }
}

// ---------------- k_tc: pure-fp16 double GEMM, double-buffered weights ----------------
__global__ __launch_bounds__(256, 2)
void k_tc(const float* __restrict__ zlp, float* __restrict__ out) {
    extern __shared__ uint32_t smw[];
    float* smf = (float*)smw;
    const uint32_t sb = smem_u32(smw);

    const int t    = threadIdx.x;
    const int lane = t & 31;
    const int wid  = t >> 5;
    const int g    = lane >> 2;
    const int tq   = lane & 3;
    const int wr   = wid >> 2;       // 0..1
    const int wc   = wid & 3;        // 0..3
    const int b0   = blockIdx.x * TMr;

    const int rowA  = lane & 15;
    const int aofs  = ((lane >> 4) & 1) * 16;
    const int rowB  = (lane & 7) + ((lane >> 4) & 1) * 8;
    const int bofs  = ((lane >> 3) & 1) * 16;

    const uint32_t aZH = sb + O_ZHI * 4 + (wr * 16 + rowA) * (STZ * 4) + aofs;
    const uint32_t bWHb = sb + O_WIH * 4 + (wc * 16 + rowB) * (STZ * 4) + bofs;
    const uint32_t aGH = sb + O_GHI * 4 + (wr * 16 + rowA) * (STG * 4) + aofs;
    const uint32_t bOHb = sb + O_WOTH * 4 + (wc * 32 + rowB) * (STG * 4) + bofs;

    // prefetch tile 0 into buf 0, overlapping z staging
    prefetch_w(sb, 0, 0, t);
    CP_COMMIT();

    // ---- stage z (fp16), once ----
#pragma unroll
    for (int it = 0; it < 8; it++) {
        int idx = t + it * 256;
        int m = idx >> 6, kp = idx & 63;
        const float* zr = zlp + (size_t)(b0 + m) * OSTRIDE + 2 * kp;
        smw[O_ZHI + m * STZ + kp] = pack_f16x2(zr[0], zr[1]);
    }

    float dz[4][4];
#pragma unroll
    for (int j = 0; j < 4; j++)
#pragma unroll
        for (int q = 0; q < 4; q++) dz[j][q] = 0.f;
    float tracc[2] = {0.f, 0.f};

    CP_WAIT0();
    __syncthreads();

#pragma unroll 1
    for (int tile = 0; tile < NT; tile++) {
        const int f0 = tile * BF;
        const int buf = tile & 1;
        const uint32_t bWH  = bWHb + (uint32_t)(buf * WIBUF) * 4u;
        const uint32_t bOH0 = bOHb + (uint32_t)(buf * WOTBUF) * 4u;
        const uint32_t bOH1 = bOH0 + 16 * (STG * 4);

        if (tile + 1 < NT) {
            prefetch_w(sb, buf ^ 1, f0 + BF, t);
            CP_COMMIT();
        }

        // ---- GEMM1: c1 = z @ wh^T  (32x64; warp tile 16m x 16f) ----
        float c1[2][4];
#pragma unroll
        for (int j = 0; j < 2; j++)
#pragma unroll
            for (int q = 0; q < 4; q++) c1[j][q] = 0.f;

#pragma unroll
        for (int kk = 0; kk < 8; kk++) {
            uint32_t ah[4], bh[4];
            ldsm_x4(ah, aZH + kk * 32);
            ldsm_x4(bh, bWH + kk * 32);
#pragma unroll
            for (int j = 0; j < 2; j++) mma_f16(c1[j], ah, bh + 2 * j);
        }

        // ---- epilogue: tanh/gate/trace, stage g (fp16) ----
#pragma unroll
        for (int j = 0; j < 2; j++) {
            const int fc = f0 + wc * 16 + j * 8 + 2 * tq;
            const float2 bi = __ldg((const float2*)(g_bias + fc));
            const float2 ga = __ldg((const float2*)(g_gate + fc));
            const float2 gs = __ldg((const float2*)(g_gs + fc));
            const int r  = wr * 16 + g;
            const int cw = wc * 8 + j * 4 + tq;
            {
                float h0 = fast_tanh(c1[j][0] + bi.x);
                float h1 = fast_tanh(c1[j][1] + bi.y);
                tracc[0] += (1.f - h0 * h0) * gs.x + (1.f - h1 * h1) * gs.y;
                smw[O_GHI + r * STG + cw] = pack_f16x2(h0 * ga.x, h1 * ga.y);
            }
            {
                float h2 = fast_tanh(c1[j][2] + bi.x);
                float h3 = fast_tanh(c1[j][3] + bi.y);
                tracc[1] += (1.f - h2 * h2) * gs.x + (1.f - h3 * h3) * gs.y;
                smw[O_GHI + (r + 8) * STG + cw] = pack_f16x2(h2 * ga.x, h3 * ga.y);
            }
        }
        __syncthreads();   // g staged before GEMM2 reads it

        // ---- GEMM2: dz += g @ wo_h (32m x 128z; warp 16m x 32z, k=64) ----
#pragma unroll
        for (int kk = 0; kk < 4; kk++) {
            uint32_t ah[4], bo_h[8];
            ldsm_x4(ah, aGH + kk * 32);
            ldsm_x4(bo_h,     bOH0 + kk * 32);
            ldsm_x4(bo_h + 4, bOH1 + kk * 32);
#pragma unroll
            for (int jn = 0; jn < 4; jn++) mma_f16(dz[jn], ah, bo_h + 2 * jn);
        }

        CP_WAIT0();
        __syncthreads();
    }

    // ---- write dz ----
    const float invF = 1.0f / (float)Fd;
#pragma unroll
    for (int jn = 0; jn < 4; jn++) {
        const int r  = b0 + wr * 16 + g;
        const int z0 = wc * 32 + jn * 8 + 2 * tq;
        out[(size_t)r * OSTRIDE + z0]           = dz[jn][0] * invF;
        out[(size_t)r * OSTRIDE + z0 + 1]       = dz[jn][1] * invF;
        out[(size_t)(r + 8) * OSTRIDE + z0]     = dz[jn][2] * invF;
        out[(size_t)(r + 8) * OSTRIDE + z0 + 1] = dz[jn][3] * invF;
    }

    // ---- trace reduction ----
    tracc[0] += __shfl_xor_sync(0xFFFFFFFFu, tracc[0], 1);
    tracc[0] += __shfl_xor_sync(0xFFFFFFFFu, tracc[0], 2);
    tracc[1] += __shfl_xor_sync(0xFFFFFFFFu, tracc[1], 1);
    tracc[1] += __shfl_xor_sync(0xFFFFFFFFu, tracc[1], 2);
    if (tq == 0) {
        smf[O_TRS + (wr * 16 + g) * 4 + wc]     = tracc[0];
        smf[O_TRS + (wr * 16 + g + 8) * 4 + wc] = tracc[1];
    }
    __syncthreads();
    if (t < TMr) {
        float s = smf[O_TRS + t * 4 + 0] + smf[O_TRS + t * 4 + 1] +
                  smf[O_TRS + t * 4 + 2] + smf[O_TRS + t * 4 + 3];
        out[(size_t)(b0 + t) * OSTRIDE + Zd] = -s * invF;
    }
}

// ---------------- launch ----------------
extern "C" void kernel_launch(void* const* d_in, const int* in_sizes, int n_in,
                              void* d_out, int out_size) {
    const float* t       = (const float*)d_in[0];
    const float* zlp     = (const float*)d_in[1];
    const float* W1      = (const float*)d_in[2];
    const float* B1      = (const float*)d_in[3];
    const float* W2      = (const float*)d_in[4];
    const float* B2      = (const float*)d_in[5];
    const float* W3_win  = (const float*)d_in[6];
    const float* b3_win  = (const float*)d_in[7];
    const float* W3_wout = (const float*)d_in[8];
    const float* b3_wout = (const float*)d_in[9];
    const float* W3_b    = (const float*)d_in[10];
    const float* b3_b    = (const float*)d_in[11];
    const float* W3_gate = (const float*)d_in[12];
    const float* b3_gate = (const float*)d_in[13];
    float* out = (float*)d_out;

    cudaFuncSetAttribute(k_tc, cudaFuncAttributeMaxDynamicSharedMemorySize, SMEM_TC);

    k_h1   <<<32,    256>>>(t, W1, B1, W2, B2);
    k_wproj<<<65536, 256>>>(W3_win, b3_win, W3_wout, b3_wout);
    k_small<<<512,   128>>>(W3_b, b3_b, W3_gate, b3_gate);
    k_tc   <<<Bd / TMr, 256, SMEM_TC>>>(zlp, out);
}

// round 16
// speedup vs baseline: 3.8355x; 1.0032x over previous
#include <cuda_runtime.h>
#include <cuda_fp16.h>
#include <math.h>
#include <stdint.h>

#define Zd  128
#define Nd  256
#define Fd  2048
#define Bd  8192
#define OSTRIDE 129   // Z+1

#define TMr 32        // batch rows per CTA
#define BF  64        // f tile
#define NT  (Fd / BF) // 32 tiles

// ---------------- device scratch ----------------
__device__ float g_h1[4][Nd];
__device__ float g_win  [Fd * Zd];
__device__ float g_wout [Fd * Zd];
__device__ float g_bias[Fd];
__device__ float g_gate[Fd];
__device__ float g_gs  [Fd];
// fp16 weights (made directly by k_wproj)
__device__ __align__(16) uint16_t g_win_h16[Fd * Zd];   // [f][z]  fp16(w_in)
__device__ __align__(16) uint16_t g_woT_h16[Zd * Fd];   // [z][f]  fp16(w_out^T)

// ---------------- smem word layout (strides ≡ 4 mod 32, rows 16B-aligned) ----------------
#define STZ 68   // 64 data words + 4 pad (272 B rows)
#define STG 36   // 32 data words + 4 pad (144 B rows)
#define WIBUF  (BF * STZ)     // 4352 words per w_in buffer
#define WOTBUF (Zd * STG)     // 4608 words per w_outT buffer
#define O_ZHI   0
#define O_WIH   (O_ZHI  + TMr * STZ)      // 2176  (2 buffers)
#define O_WOTH  (O_WIH  + 2 * WIBUF)      // 10880 (2 buffers)
#define O_GHI   (O_WOTH + 2 * WOTBUF)     // 20096
#define O_TRS   (O_GHI  + TMr * STG)      // 21248
#define O_BIAS  (O_TRS  + TMr * 4)        // 21376
#define O_GATE  (O_BIAS + Fd)             // 23424
#define O_GS    (O_GATE + Fd)             // 25472
#define SMEMW   (O_GS   + Fd)             // 27520 words
#define SMEM_TC (SMEMW * 4)               // 110080 B -> 2 CTAs/SM (220 KB <= 228 KB)

// ---------------- helpers ----------------
__device__ __forceinline__ uint32_t smem_u32(const void* p) {
    uint32_t a;
    asm("{ .reg .u64 t; cvta.to.shared.u64 t, %1; cvt.u32.u64 %0, t; }" : "=r"(a) : "l"(p));
    return a;
}
__device__ __forceinline__ void ldsm_x4(uint32_t* r, uint32_t addr) {
    asm volatile("ldmatrix.sync.aligned.m8n8.x4.shared.b16 {%0,%1,%2,%3}, [%4];"
                 : "=r"(r[0]), "=r"(r[1]), "=r"(r[2]), "=r"(r[3]) : "r"(addr));
}
#define CP_ASYNC16(dst, src) asm volatile("cp.async.cg.shared.global [%0], [%1], 16;" :: "r"(dst), "l"(src))
#define CP_COMMIT()          asm volatile("cp.async.commit_group;" ::: "memory")
#define CP_WAIT0()           asm volatile("cp.async.wait_group 0;" ::: "memory")

__device__ __forceinline__ uint32_t pack_f16x2(float a, float b) {
    __half2 h = __floats2half2_rn(a, b);
    return *(uint32_t*)&h;
}
__device__ __forceinline__ float fast_tanh(float x) {
    float y;
    asm("tanh.approx.f32 %0, %1;" : "=f"(y) : "f"(x));
    return y;
}
__device__ __forceinline__ void mma_f16(float* c, const uint32_t* a, const uint32_t* b) {
    asm volatile(
        "mma.sync.aligned.m16n8k16.row.col.f32.f16.f16.f32 "
        "{%0,%1,%2,%3}, {%4,%5,%6,%7}, {%8,%9}, {%0,%1,%2,%3};"
        : "+f"(c[0]), "+f"(c[1]), "+f"(c[2]), "+f"(c[3])
        : "r"(a[0]), "r"(a[1]), "r"(a[2]), "r"(a[3]), "r"(b[0]), "r"(b[1]));
}

// ---------------- kernel 1: hypernet h0 -> h1 (32 blocks) ----------------
__global__ void k_h1(const float* __restrict__ tt,
                     const float* __restrict__ W1, const float* __restrict__ B1,
                     const float* __restrict__ W2, const float* __restrict__ B2) {
    __shared__ float h0[Nd];
    const int k   = blockIdx.x >> 3;
    const int blk = blockIdx.x & 7;
    const int t   = threadIdx.x;
    const float ts = tt[0];
    h0[t] = tanhf(fmaf(W1[k * Nd + t], ts, B1[k * Nd + t]));
    __syncthreads();

    const int wid  = t >> 5;
    const int lane = t & 31;
    const float4* h4 = (const float4*)h0;
#pragma unroll
    for (int r = 0; r < 4; r++) {
        const int n = blk * 32 + wid * 4 + r;
        const float4* w2 = (const float4*)(W2 + ((size_t)k * Nd + n) * Nd);
        float acc = 0.f;
#pragma unroll
        for (int i = 0; i < 2; i++) {
            float4 v = w2[lane + i * 32];
            float4 h = h4[lane + i * 32];
            acc = fmaf(v.x, h.x, fmaf(v.y, h.y, fmaf(v.z, h.z, fmaf(v.w, h.w, acc))));
        }
#pragma unroll
        for (int o = 16; o > 0; o >>= 1) acc += __shfl_xor_sync(0xFFFFFFFFu, acc, o);
        if (lane == 0) g_h1[k][n] = tanhf(acc + B2[k * Nd + n]);
    }
}

// ---------------- kernel 2: w_in / w_out matvecs (+ direct fp16 emit) ----------------
__global__ void k_wproj(const float* __restrict__ W3_win,  const float* __restrict__ b3_win,
                        const float* __restrict__ W3_wout, const float* __restrict__ b3_wout) {
    __shared__ float h1a[Nd], h1b[Nd];
    const int t = threadIdx.x;
    h1a[t] = g_h1[0][t];
    h1b[t] = g_h1[1][t];
    __syncthreads();

    const int wid  = t >> 5;
    const int lane = t & 31;
    long r = (long)blockIdx.x * 8 + wid;

    const float* wmat; const float* bias; const float* hv; long rr; int isOut;
    if (r < (long)Fd * Zd) { rr = r;                 wmat = W3_win;  bias = b3_win;  hv = h1a; isOut = 0; }
    else                   { rr = r - (long)Fd * Zd; wmat = W3_wout; bias = b3_wout; hv = h1b; isOut = 1; }

    const float4* __restrict__ row = (const float4*)(wmat + rr * Nd);
    const float4* __restrict__ hv4 = (const float4*)hv;
    float acc = 0.f;
#pragma unroll
    for (int i = 0; i < 2; i++) {
        float4 v = row[lane + i * 32];
        float4 h = hv4[lane + i * 32];
        acc = fmaf(v.x, h.x, acc);
        acc = fmaf(v.y, h.y, acc);
        acc = fmaf(v.z, h.z, acc);
        acc = fmaf(v.w, h.w, acc);
    }
#pragma unroll
    for (int o = 16; o > 0; o >>= 1) acc += __shfl_xor_sync(0xFFFFFFFFu, acc, o);
    if (lane == 0) {
        float v = acc + bias[rr];
        uint16_t v16 = __half_as_ushort(__float2half_rn(v));
        if (isOut) {
            g_wout[rr] = v;
            int f = (int)(rr >> 7);
            int z = (int)(rr & 127);
            g_woT_h16[(size_t)z * Fd + f] = v16;
        } else {
            g_win[rr] = v;
            g_win_h16[rr] = v16;
        }
    }
}

// ---------------- kernel 3: bias, gate, gate*s ----------------
__global__ void k_small(const float* __restrict__ W3_b,    const float* __restrict__ b3_b,
                        const float* __restrict__ W3_gate, const float* __restrict__ b3_gate) {
    __shared__ float h2[Nd], h3[Nd];
    const int t = threadIdx.x;
    h2[t] = g_h1[2][t];  h2[t + 128] = g_h1[2][t + 128];
    h3[t] = g_h1[3][t];  h3[t + 128] = g_h1[3][t + 128];
    __syncthreads();

    const int wid  = t >> 5;
    const int lane = t & 31;
    const int f = blockIdx.x * 4 + wid;

    const float4* rb = (const float4*)(W3_b    + (size_t)f * Nd);
    const float4* rg = (const float4*)(W3_gate + (size_t)f * Nd);
    const float4* h2v = (const float4*)h2;
    const float4* h3v = (const float4*)h3;

    float accb = 0.f, accg = 0.f;
#pragma unroll
    for (int i = 0; i < 2; i++) {
        float4 v = rb[lane + i * 32], h = h2v[lane + i * 32];
        accb = fmaf(v.x, h.x, fmaf(v.y, h.y, fmaf(v.z, h.z, fmaf(v.w, h.w, accb))));
        float4 v2 = rg[lane + i * 32], h4 = h3v[lane + i * 32];
        accg = fmaf(v2.x, h4.x, fmaf(v2.y, h4.y, fmaf(v2.z, h4.z, fmaf(v2.w, h4.w, accg))));
    }
    const float4 a  = ((const float4*)(g_win  + (size_t)f * Zd))[lane];
    const float4 b4 = ((const float4*)(g_wout + (size_t)f * Zd))[lane];
    float accs = a.x * b4.x + a.y * b4.y + a.z * b4.z + a.w * b4.w;

#pragma unroll
    for (int o = 16; o > 0; o >>= 1) {
        accb += __shfl_xor_sync(0xFFFFFFFFu, accb, o);
        accg += __shfl_xor_sync(0xFFFFFFFFu, accg, o);
        accs += __shfl_xor_sync(0xFFFFFFFFu, accs, o);
    }
    if (lane == 0) {
        g_bias[f] = accb + b3_b[f];
        float gt = 1.f / (1.f + expf(-(accg + b3_gate[f])));
        g_gate[f] = gt;
        g_gs[f]   = gt * accs;
    }
}

// ---------------- weight tile prefetch (cp.async, 8 x 16B per thread) ----------------
__device__ __forceinline__ void prefetch_w(uint32_t sb, int buf, int f0, int t) {
#pragma unroll
    for (int it = 0; it < 4; it++) {
        int idx = t + it * 256;            // 0..1023
        int fi = idx >> 4, seg = idx & 15;
        uint32_t dst = sb + (uint32_t)(O_WIH + buf * WIBUF + fi * STZ + seg * 4) * 4u;
        CP_ASYNC16(dst, g_win_h16 + (size_t)(f0 + fi) * Zd + seg * 8);
    }
#pragma unroll
    for (int it = 0; it < 4; it++) {
        int idx = t + it * 256;            // 0..1023
        int z = idx >> 3, seg = idx & 7;
        uint32_t dst = sb + (uint32_t)(O_WOTH + buf * WOTBUF + z * STG + seg * 4) * 4u;
        CP_ASYNC16(dst, g_woT_h16 + (size_t)z * Fd + f0 + seg * 8);
    }
}

// ---------------- k_tc: pure-fp16 double GEMM, double-buffered weights ----------------
__global__ __launch_bounds__(256, 2)
void k_tc(const float* __restrict__ zlp, float* __restrict__ out) {
    extern __shared__ uint32_t smw[];
    float* smf = (float*)smw;
    const uint32_t sb = smem_u32(smw);

    const int t    = threadIdx.x;
    const int lane = t & 31;
    const int wid  = t >> 5;
    const int g    = lane >> 2;
    const int tq   = lane & 3;
    const int wr   = wid >> 2;       // 0..1
    const int wc   = wid & 3;        // 0..3
    const int b0   = blockIdx.x * TMr;

    const int rowA  = lane & 15;
    const int aofs  = ((lane >> 4) & 1) * 16;
    const int rowB  = (lane & 7) + ((lane >> 4) & 1) * 8;
    const int bofs  = ((lane >> 3) & 1) * 16;

    const uint32_t aZH = sb + O_ZHI * 4 + (wr * 16 + rowA) * (STZ * 4) + aofs;
    const uint32_t bWHb = sb + O_WIH * 4 + (wc * 16 + rowB) * (STZ * 4) + bofs;
    const uint32_t aGH = sb + O_GHI * 4 + (wr * 16 + rowA) * (STG * 4) + aofs;
    const uint32_t bOHb = sb + O_WOTH * 4 + (wc * 32 + rowB) * (STG * 4) + bofs;

    // prefetch tile 0 into buf 0, overlapping z + bias/gate/gs staging
    prefetch_w(sb, 0, 0, t);
    CP_COMMIT();

    // ---- stage z (fp16), once ----
#pragma unroll
    for (int it = 0; it < 8; it++) {
        int idx = t + it * 256;
        int m = idx >> 6, kp = idx & 63;
        const float* zr = zlp + (size_t)(b0 + m) * OSTRIDE + 2 * kp;
        smw[O_ZHI + m * STZ + kp] = pack_f16x2(zr[0], zr[1]);
    }
    // ---- stage bias/gate/gs (fp32), once ----
#pragma unroll
    for (int i = 0; i < Fd / 256; i++) {
        int idx = t + i * 256;
        smf[O_BIAS + idx] = g_bias[idx];
        smf[O_GATE + idx] = g_gate[idx];
        smf[O_GS   + idx] = g_gs[idx];
    }

    float dz[4][4];
#pragma unroll
    for (int j = 0; j < 4; j++)
#pragma unroll
        for (int q = 0; q < 4; q++) dz[j][q] = 0.f;
    float tracc[2] = {0.f, 0.f};

    CP_WAIT0();
    __syncthreads();

#pragma unroll 1
    for (int tile = 0; tile < NT; tile++) {
        const int f0 = tile * BF;
        const int buf = tile & 1;
        const uint32_t bWH  = bWHb + (uint32_t)(buf * WIBUF) * 4u;
        const uint32_t bOH0 = bOHb + (uint32_t)(buf * WOTBUF) * 4u;
        const uint32_t bOH1 = bOH0 + 16 * (STG * 4);

        if (tile + 1 < NT) {
            prefetch_w(sb, buf ^ 1, f0 + BF, t);
            CP_COMMIT();
        }

        // ---- GEMM1: c1 = z @ wh^T  (32x64; warp tile 16m x 16f) ----
        float c1[2][4];
#pragma unroll
        for (int j = 0; j < 2; j++)
#pragma unroll
            for (int q = 0; q < 4; q++) c1[j][q] = 0.f;

#pragma unroll
        for (int kk = 0; kk < 8; kk++) {
            uint32_t ah[4], bh[4];
            ldsm_x4(ah, aZH + kk * 32);
            ldsm_x4(bh, bWH + kk * 32);
#pragma unroll
            for (int j = 0; j < 2; j++) mma_f16(c1[j], ah, bh + 2 * j);
        }

        // ---- epilogue: tanh/gate/trace, stage g (fp16) ----
#pragma unroll
        for (int j = 0; j < 2; j++) {
            const int fc = f0 + wc * 16 + j * 8 + 2 * tq;
            const float2 bi = *(const float2*)(smf + O_BIAS + fc);
            const float2 ga = *(const float2*)(smf + O_GATE + fc);
            const float2 gs = *(const float2*)(smf + O_GS + fc);
            const int r  = wr * 16 + g;
            const int cw = wc * 8 + j * 4 + tq;
            {
                float h0 = fast_tanh(c1[j][0] + bi.x);
                float h1 = fast_tanh(c1[j][1] + bi.y);
                tracc[0] += (1.f - h0 * h0) * gs.x + (1.f - h1 * h1) * gs.y;
                smw[O_GHI + r * STG + cw] = pack_f16x2(h0 * ga.x, h1 * ga.y);
            }
            {
                float h2 = fast_tanh(c1[j][2] + bi.x);
                float h3 = fast_tanh(c1[j][3] + bi.y);
                tracc[1] += (1.f - h2 * h2) * gs.x + (1.f - h3 * h3) * gs.y;
                smw[O_GHI + (r + 8) * STG + cw] = pack_f16x2(h2 * ga.x, h3 * ga.y);
            }
        }
        __syncthreads();   // g staged before GEMM2 reads it

        // ---- GEMM2: dz += g @ wo_h (32m x 128z; warp 16m x 32z, k=64) ----
#pragma unroll
        for (int kk = 0; kk < 4; kk++) {
            uint32_t ah[4], bo_h[8];
            ldsm_x4(ah, aGH + kk * 32);
            ldsm_x4(bo_h,     bOH0 + kk * 32);
            ldsm_x4(bo_h + 4, bOH1 + kk * 32);
#pragma unroll
            for (int jn = 0; jn < 4; jn++) mma_f16(dz[jn], ah, bo_h + 2 * jn);
        }

        CP_WAIT0();
        __syncthreads();
    }

    // ---- write dz ----
    const float invF = 1.0f / (float)Fd;
#pragma unroll
    for (int jn = 0; jn < 4; jn++) {
        const int r  = b0 + wr * 16 + g;
        const int z0 = wc * 32 + jn * 8 + 2 * tq;
        out[(size_t)r * OSTRIDE + z0]           = dz[jn][0] * invF;
        out[(size_t)r * OSTRIDE + z0 + 1]       = dz[jn][1] * invF;
        out[(size_t)(r + 8) * OSTRIDE + z0]     = dz[jn][2] * invF;
        out[(size_t)(r + 8) * OSTRIDE + z0 + 1] = dz[jn][3] * invF;
    }

    // ---- trace reduction ----
    tracc[0] += __shfl_xor_sync(0xFFFFFFFFu, tracc[0], 1);
    tracc[0] += __shfl_xor_sync(0xFFFFFFFFu, tracc[0], 2);
    tracc[1] += __shfl_xor_sync(0xFFFFFFFFu, tracc[1], 1);
    tracc[1] += __shfl_xor_sync(0xFFFFFFFFu, tracc[1], 2);
    if (tq == 0) {
        smf[O_TRS + (wr * 16 + g) * 4 + wc]     = tracc[0];
        smf[O_TRS + (wr * 16 + g + 8) * 4 + wc] = tracc[1];
    }
    __syncthreads();
    if (t < TMr) {
        float s = smf[O_TRS + t * 4 + 0] + smf[O_TRS + t * 4 + 1] +
                  smf[O_TRS + t * 4 + 2] + smf[O_TRS + t * 4 + 3];
        out[(size_t)(b0 + t) * OSTRIDE + Zd] = -s * invF;
    }
}

// ---------------- launch ----------------
extern "C" void kernel_launch(void* const* d_in, const int* in_sizes, int n_in,
                              void* d_out, int out_size) {
    const float* t       = (const float*)d_in[0];
    const float* zlp     = (const float*)d_in[1];
    const float* W1      = (const float*)d_in[2];
    const float* B1      = (const float*)d_in[3];
    const float* W2      = (const float*)d_in[4];
    const float* B2      = (const float*)d_in[5];
    const float* W3_win  = (const float*)d_in[6];
    const float* b3_win  = (const float*)d_in[7];
    const float* W3_wout = (const float*)d_in[8];
    const float* b3_wout = (const float*)d_in[9];
    const float* W3_b    = (const float*)d_in[10];
    const float* b3_b    = (const float*)d_in[11];
    const float* W3_gate = (const float*)d_in[12];
    const float* b3_gate = (const float*)d_in[13];
    float* out = (float*)d_out;

    cudaFuncSetAttribute(k_tc, cudaFuncAttributeMaxDynamicSharedMemorySize, SMEM_TC);

    k_h1   <<<32,    256>>>(t, W1, B1, W2, B2);
    k_wproj<<<65536, 256>>>(W3_win, b3_win, W3_wout, b3_wout);
    k_small<<<512,   128>>>(W3_b, b3_b, W3_gate, b3_gate);
    k_tc   <<<Bd / TMr, 256, SMEM_TC>>>(zlp, out);
}

// round 17
// speedup vs baseline: 4.1774x; 1.0892x over previous
#include <cuda_runtime.h>
#include <cuda_fp16.h>
#include <math.h>
#include <stdint.h>

#define Zd  128
#define Nd  256
#define Fd  2048
#define Bd  8192
#define OSTRIDE 129   // Z+1

#define TMr 32        // batch rows per CTA
#define BF  64        // f tile
#define NT  (Fd / BF) // 32 tiles

// ---------------- device scratch ----------------
__device__ float g_h1[4][Nd];
__device__ float g_win  [Fd * Zd];
__device__ float g_wout [Fd * Zd];
__device__ float g_bias[Fd];
__device__ float g_gate[Fd];
__device__ float g_gs  [Fd];
// fp16 weights (made directly by k_wproj)
__device__ __align__(16) uint16_t g_win_h16[Fd * Zd];   // [f][z]  fp16(w_in)
__device__ __align__(16) uint16_t g_woT_h16[Zd * Fd];   // [z][f]  fp16(w_out^T)

// ---------------- smem word layout (strides ≡ 4 mod 32, rows 16B-aligned) ----------------
#define STZ 68   // 64 data words + 4 pad (272 B rows)
#define STG 36   // 32 data words + 4 pad (144 B rows)
#define WIBUF  (BF * STZ)     // 4352 words per w_in buffer
#define WOTBUF (Zd * STG)     // 4608 words per w_outT buffer
#define O_ZHI   0
#define O_WIH   (O_ZHI  + TMr * STZ)      // 2176  (2 buffers)
#define O_WOTH  (O_WIH  + 2 * WIBUF)      // 10880 (2 buffers)
#define O_GHI   (O_WOTH + 2 * WOTBUF)     // 20096
#define O_TRS   (O_GHI  + TMr * STG)      // 21248
#define SMEMW   (O_TRS  + TMr * 4)        // 21376 words
#define SMEM_TC (SMEMW * 4)               // 85504 B -> 2 CTAs/SM

// ---------------- helpers ----------------
__device__ __forceinline__ uint32_t smem_u32(const void* p) {
    uint32_t a;
    asm("{ .reg .u64 t; cvta.to.shared.u64 t, %1; cvt.u32.u64 %0, t; }" : "=r"(a) : "l"(p));
    return a;
}
__device__ __forceinline__ void ldsm_x4(uint32_t* r, uint32_t addr) {
    asm volatile("ldmatrix.sync.aligned.m8n8.x4.shared.b16 {%0,%1,%2,%3}, [%4];"
                 : "=r"(r[0]), "=r"(r[1]), "=r"(r[2]), "=r"(r[3]) : "r"(addr));
}
#define CP_ASYNC16(dst, src) asm volatile("cp.async.cg.shared.global [%0], [%1], 16;" :: "r"(dst), "l"(src))
#define CP_COMMIT()          asm volatile("cp.async.commit_group;" ::: "memory")
#define CP_WAIT0()           asm volatile("cp.async.wait_group 0;" ::: "memory")

__device__ __forceinline__ uint32_t pack_f16x2(float a, float b) {
    __half2 h = __floats2half2_rn(a, b);
    return *(uint32_t*)&h;
}
__device__ __forceinline__ float fast_tanh(float x) {
    float y;
    asm("tanh.approx.f32 %0, %1;" : "=f"(y) : "f"(x));
    return y;
}
__device__ __forceinline__ void mma_f16(float* c, const uint32_t* a, const uint32_t* b) {
    asm volatile(
        "mma.sync.aligned.m16n8k16.row.col.f32.f16.f16.f32 "
        "{%0,%1,%2,%3}, {%4,%5,%6,%7}, {%8,%9}, {%0,%1,%2,%3};"
        : "+f"(c[0]), "+f"(c[1]), "+f"(c[2]), "+f"(c[3])
        : "r"(a[0]), "r"(a[1]), "r"(a[2]), "r"(a[3]), "r"(b[0]), "r"(b[1]));
}

// ---------------- kernel 1: hypernet h0 -> h1 (32 blocks) ----------------
__global__ void k_h1(const float* __restrict__ tt,
                     const float* __restrict__ W1, const float* __restrict__ B1,
                     const float* __restrict__ W2, const float* __restrict__ B2) {
    __shared__ float h0[Nd];
    const int k   = blockIdx.x >> 3;
    const int blk = blockIdx.x & 7;
    const int t   = threadIdx.x;
    const float ts = tt[0];
    h0[t] = tanhf(fmaf(W1[k * Nd + t], ts, B1[k * Nd + t]));
    __syncthreads();

    const int wid  = t >> 5;
    const int lane = t & 31;
    const float4* h4 = (const float4*)h0;
#pragma unroll
    for (int r = 0; r < 4; r++) {
        const int n = blk * 32 + wid * 4 + r;
        const float4* w2 = (const float4*)(W2 + ((size_t)k * Nd + n) * Nd);
        float acc = 0.f;
#pragma unroll
        for (int i = 0; i < 2; i++) {
            float4 v = w2[lane + i * 32];
            float4 h = h4[lane + i * 32];
            acc = fmaf(v.x, h.x, fmaf(v.y, h.y, fmaf(v.z, h.z, fmaf(v.w, h.w, acc))));
        }
#pragma unroll
        for (int o = 16; o > 0; o >>= 1) acc += __shfl_xor_sync(0xFFFFFFFFu, acc, o);
        if (lane == 0) g_h1[k][n] = tanhf(acc + B2[k * Nd + n]);
    }
}

// ---------------- kernel 2: w_in / w_out matvecs, 2 rows per warp ----------------
__global__ void k_wproj(const float* __restrict__ W3_win,  const float* __restrict__ b3_win,
                        const float* __restrict__ W3_wout, const float* __restrict__ b3_wout) {
    __shared__ float h1a[Nd], h1b[Nd];
    const int t = threadIdx.x;
    h1a[t] = g_h1[0][t];
    h1b[t] = g_h1[1][t];
    __syncthreads();

    const int wid  = t >> 5;
    const int lane = t & 31;
    long r0 = ((long)blockIdx.x * 8 + wid) * 2;   // two consecutive rows per warp

    const float* wmat; const float* bias; const float* hv; long rr; int isOut;
    if (r0 < (long)Fd * Zd) { rr = r0;                 wmat = W3_win;  bias = b3_win;  hv = h1a; isOut = 0; }
    else                    { rr = r0 - (long)Fd * Zd; wmat = W3_wout; bias = b3_wout; hv = h1b; isOut = 1; }

    const float4* __restrict__ rowA = (const float4*)(wmat + rr * Nd);
    const float4* __restrict__ rowB = (const float4*)(wmat + (rr + 1) * Nd);
    const float4* __restrict__ hv4  = (const float4*)hv;

    // issue all 8 loads up front (MLP)
    float4 a0 = rowA[lane],      a1 = rowA[lane + 32];
    float4 b0 = rowB[lane],      b1 = rowB[lane + 32];
    float4 h0 = hv4[lane],       h1 = hv4[lane + 32];

    float accA = 0.f, accB = 0.f;
    accA = fmaf(a0.x, h0.x, fmaf(a0.y, h0.y, fmaf(a0.z, h0.z, fmaf(a0.w, h0.w, accA))));
    accB = fmaf(b0.x, h0.x, fmaf(b0.y, h0.y, fmaf(b0.z, h0.z, fmaf(b0.w, h0.w, accB))));
    accA = fmaf(a1.x, h1.x, fmaf(a1.y, h1.y, fmaf(a1.z, h1.z, fmaf(a1.w, h1.w, accA))));
    accB = fmaf(b1.x, h1.x, fmaf(b1.y, h1.y, fmaf(b1.z, h1.z, fmaf(b1.w, h1.w, accB))));

#pragma unroll
    for (int o = 16; o > 0; o >>= 1) {
        accA += __shfl_xor_sync(0xFFFFFFFFu, accA, o);
        accB += __shfl_xor_sync(0xFFFFFFFFu, accB, o);
    }
    if (lane == 0) {
        float vA = accA + bias[rr];
        float vB = accB + bias[rr + 1];
        uint16_t vA16 = __half_as_ushort(__float2half_rn(vA));
        uint16_t vB16 = __half_as_ushort(__float2half_rn(vB));
        if (isOut) {
            g_wout[rr]     = vA;
            g_wout[rr + 1] = vB;
            int f  = (int)(rr >> 7);
            int z  = (int)(rr & 127);
            int f2 = (int)((rr + 1) >> 7);
            int z2 = (int)((rr + 1) & 127);
            g_woT_h16[(size_t)z  * Fd + f]  = vA16;
            g_woT_h16[(size_t)z2 * Fd + f2] = vB16;
        } else {
            g_win[rr]     = vA;
            g_win[rr + 1] = vB;
            g_win_h16[rr]     = vA16;
            g_win_h16[rr + 1] = vB16;
        }
    }
}

// ---------------- kernel 3: bias, gate, gate*s ----------------
__global__ void k_small(const float* __restrict__ W3_b,    const float* __restrict__ b3_b,
                        const float* __restrict__ W3_gate, const float* __restrict__ b3_gate) {
    __shared__ float h2[Nd], h3[Nd];
    const int t = threadIdx.x;
    h2[t] = g_h1[2][t];  h2[t + 128] = g_h1[2][t + 128];
    h3[t] = g_h1[3][t];  h3[t + 128] = g_h1[3][t + 128];
    __syncthreads();

    const int wid  = t >> 5;
    const int lane = t & 31;
    const int f = blockIdx.x * 4 + wid;

    const float4* rb = (const float4*)(W3_b    + (size_t)f * Nd);
    const float4* rg = (const float4*)(W3_gate + (size_t)f * Nd);
    const float4* h2v = (const float4*)h2;
    const float4* h3v = (const float4*)h3;

    float accb = 0.f, accg = 0.f;
#pragma unroll
    for (int i = 0; i < 2; i++) {
        float4 v = rb[lane + i * 32], h = h2v[lane + i * 32];
        accb = fmaf(v.x, h.x, fmaf(v.y, h.y, fmaf(v.z, h.z, fmaf(v.w, h.w, accb))));
        float4 v2 = rg[lane + i * 32], h4 = h3v[lane + i * 32];
        accg = fmaf(v2.x, h4.x, fmaf(v2.y, h4.y, fmaf(v2.z, h4.z, fmaf(v2.w, h4.w, accg))));
    }
    const float4 a  = ((const float4*)(g_win  + (size_t)f * Zd))[lane];
    const float4 b4 = ((const float4*)(g_wout + (size_t)f * Zd))[lane];
    float accs = a.x * b4.x + a.y * b4.y + a.z * b4.z + a.w * b4.w;

#pragma unroll
    for (int o = 16; o > 0; o >>= 1) {
        accb += __shfl_xor_sync(0xFFFFFFFFu, accb, o);
        accg += __shfl_xor_sync(0xFFFFFFFFu, accg, o);
        accs += __shfl_xor_sync(0xFFFFFFFFu, accs, o);
    }
    if (lane == 0) {
        g_bias[f] = accb + b3_b[f];
        float gt = 1.f / (1.f + expf(-(accg + b3_gate[f])));
        g_gate[f] = gt;
        g_gs[f]   = gt * accs;
    }
}

// ---------------- weight tile prefetch (cp.async, 8 x 16B per thread) ----------------
__device__ __forceinline__ void prefetch_w(uint32_t sb, int buf, int f0, int t) {
#pragma unroll
    for (int it = 0; it < 4; it++) {
        int idx = t + it * 256;            // 0..1023
        int fi = idx >> 4, seg = idx & 15;
        uint32_t dst = sb + (uint32_t)(O_WIH + buf * WIBUF + fi * STZ + seg * 4) * 4u;
        CP_ASYNC16(dst, g_win_h16 + (size_t)(f0 + fi) * Zd + seg * 8);
    }
#pragma unroll
    for (int it = 0; it < 4; it++) {
        int idx = t + it * 256;            // 0..1023
        int z = idx >> 3, seg = idx & 7;
        uint32_t dst = sb + (uint32_t)(O_WOTH + buf * WOTBUF + z * STG + seg * 4) * 4u;
        CP_ASYNC16(dst, g_woT_h16 + (size_t)z * Fd + f0 + seg * 8);
    }
}

// ---------------- k_tc: pure-fp16 double GEMM, double-buffered weights ----------------
__global__ __launch_bounds__(256, 2)
void k_tc(const float* __restrict__ zlp, float* __restrict__ out) {
    extern __shared__ uint32_t smw[];
    float* smf = (float*)smw;
    const uint32_t sb = smem_u32(smw);

    const int t    = threadIdx.x;
    const int lane = t & 31;
    const int wid  = t >> 5;
    const int g    = lane >> 2;
    const int tq   = lane & 3;
    const int wr   = wid >> 2;       // 0..1
    const int wc   = wid & 3;        // 0..3
    const int b0   = blockIdx.x * TMr;

    const int rowA  = lane & 15;
    const int aofs  = ((lane >> 4) & 1) * 16;
    const int rowB  = (lane & 7) + ((lane >> 4) & 1) * 8;
    const int bofs  = ((lane >> 3) & 1) * 16;

    const uint32_t aZH = sb + O_ZHI * 4 + (wr * 16 + rowA) * (STZ * 4) + aofs;
    const uint32_t bWHb = sb + O_WIH * 4 + (wc * 16 + rowB) * (STZ * 4) + bofs;
    const uint32_t aGH = sb + O_GHI * 4 + (wr * 16 + rowA) * (STG * 4) + aofs;
    const uint32_t bOHb = sb + O_WOTH * 4 + (wc * 32 + rowB) * (STG * 4) + bofs;

    // prefetch tile 0 into buf 0, overlapping z staging
    prefetch_w(sb, 0, 0, t);
    CP_COMMIT();

    // ---- stage z (fp16), once ----
#pragma unroll
    for (int it = 0; it < 8; it++) {
        int idx = t + it * 256;
        int m = idx >> 6, kp = idx & 63;
        const float* zr = zlp + (size_t)(b0 + m) * OSTRIDE + 2 * kp;
        smw[O_ZHI + m * STZ + kp] = pack_f16x2(zr[0], zr[1]);
    }

    float dz[4][4];
#pragma unroll
    for (int j = 0; j < 4; j++)
#pragma unroll
        for (int q = 0; q < 4; q++) dz[j][q] = 0.f;
    float tracc[2] = {0.f, 0.f};

    CP_WAIT0();
    __syncthreads();

#pragma unroll 1
    for (int tile = 0; tile < NT; tile++) {
        const int f0 = tile * BF;
        const int buf = tile & 1;
        const uint32_t bWH  = bWHb + (uint32_t)(buf * WIBUF) * 4u;
        const uint32_t bOH0 = bOHb + (uint32_t)(buf * WOTBUF) * 4u;
        const uint32_t bOH1 = bOH0 + 16 * (STG * 4);

        if (tile + 1 < NT) {
            prefetch_w(sb, buf ^ 1, f0 + BF, t);
            CP_COMMIT();
        }

        // ---- GEMM1: c1 = z @ wh^T  (32x64; warp tile 16m x 16f) ----
        float c1[2][4];
#pragma unroll
        for (int j = 0; j < 2; j++)
#pragma unroll
            for (int q = 0; q < 4; q++) c1[j][q] = 0.f;

#pragma unroll
        for (int kk = 0; kk < 8; kk++) {
            uint32_t ah[4], bh[4];
            ldsm_x4(ah, aZH + kk * 32);
            ldsm_x4(bh, bWH + kk * 32);
#pragma unroll
            for (int j = 0; j < 2; j++) mma_f16(c1[j], ah, bh + 2 * j);
        }

        // ---- epilogue: tanh/gate/trace, stage g (fp16) ----
#pragma unroll
        for (int j = 0; j < 2; j++) {
            const int fc = f0 + wc * 16 + j * 8 + 2 * tq;
            const float2 bi = __ldg((const float2*)(g_bias + fc));
            const float2 ga = __ldg((const float2*)(g_gate + fc));
            const float2 gs = __ldg((const float2*)(g_gs + fc));
            const int r  = wr * 16 + g;
            const int cw = wc * 8 + j * 4 + tq;
            {
                float h0 = fast_tanh(c1[j][0] + bi.x);
                float h1 = fast_tanh(c1[j][1] + bi.y);
                tracc[0] += (1.f - h0 * h0) * gs.x + (1.f - h1 * h1) * gs.y;
                smw[O_GHI + r * STG + cw] = pack_f16x2(h0 * ga.x, h1 * ga.y);
            }
            {
                float h2 = fast_tanh(c1[j][2] + bi.x);
                float h3 = fast_tanh(c1[j][3] + bi.y);
                tracc[1] += (1.f - h2 * h2) * gs.x + (1.f - h3 * h3) * gs.y;
                smw[O_GHI + (r + 8) * STG + cw] = pack_f16x2(h2 * ga.x, h3 * ga.y);
            }
        }
        __syncthreads();   // g staged before GEMM2 reads it

        // ---- GEMM2: dz += g @ wo_h (32m x 128z; warp 16m x 32z, k=64) ----
#pragma unroll
        for (int kk = 0; kk < 4; kk++) {
            uint32_t ah[4], bo_h[8];
            ldsm_x4(ah, aGH + kk * 32);
            ldsm_x4(bo_h,     bOH0 + kk * 32);
            ldsm_x4(bo_h + 4, bOH1 + kk * 32);
#pragma unroll
            for (int jn = 0; jn < 4; jn++) mma_f16(dz[jn], ah, bo_h + 2 * jn);
        }

        CP_WAIT0();
        __syncthreads();
    }

    // ---- write dz ----
    const float invF = 1.0f / (float)Fd;
#pragma unroll
    for (int jn = 0; jn < 4; jn++) {
        const int r  = b0 + wr * 16 + g;
        const int z0 = wc * 32 + jn * 8 + 2 * tq;
        out[(size_t)r * OSTRIDE + z0]           = dz[jn][0] * invF;
        out[(size_t)r * OSTRIDE + z0 + 1]       = dz[jn][1] * invF;
        out[(size_t)(r + 8) * OSTRIDE + z0]     = dz[jn][2] * invF;
        out[(size_t)(r + 8) * OSTRIDE + z0 + 1] = dz[jn][3] * invF;
    }

    // ---- trace reduction ----
    tracc[0] += __shfl_xor_sync(0xFFFFFFFFu, tracc[0], 1);
    tracc[0] += __shfl_xor_sync(0xFFFFFFFFu, tracc[0], 2);
    tracc[1] += __shfl_xor_sync(0xFFFFFFFFu, tracc[1], 1);
    tracc[1] += __shfl_xor_sync(0xFFFFFFFFu, tracc[1], 2);
    if (tq == 0) {
        smf[O_TRS + (wr * 16 + g) * 4 + wc]     = tracc[0];
        smf[O_TRS + (wr * 16 + g + 8) * 4 + wc] = tracc[1];
    }
    __syncthreads();
    if (t < TMr) {
        float s = smf[O_TRS + t * 4 + 0] + smf[O_TRS + t * 4 + 1] +
                  smf[O_TRS + t * 4 + 2] + smf[O_TRS + t * 4 + 3];
        out[(size_t)(b0 + t) * OSTRIDE + Zd] = -s * invF;
    }
}

// ---------------- launch ----------------
extern "C" void kernel_launch(void* const* d_in, const int* in_sizes, int n_in,
                              void* d_out, int out_size) {
    const float* t       = (const float*)d_in[0];
    const float* zlp     = (const float*)d_in[1];
    const float* W1      = (const float*)d_in[2];
    const float* B1      = (const float*)d_in[3];
    const float* W2      = (const float*)d_in[4];
    const float* B2      = (const float*)d_in[5];
    const float* W3_win  = (const float*)d_in[6];
    const float* b3_win  = (const float*)d_in[7];
    const float* W3_wout = (const float*)d_in[8];
    const float* b3_wout = (const float*)d_in[9];
    const float* W3_b    = (const float*)d_in[10];
    const float* b3_b    = (const float*)d_in[11];
    const float* W3_gate = (const float*)d_in[12];
    const float* b3_gate = (const float*)d_in[13];
    float* out = (float*)d_out;

    cudaFuncSetAttribute(k_tc, cudaFuncAttributeMaxDynamicSharedMemorySize, SMEM_TC);

    k_h1   <<<32,    256>>>(t, W1, B1, W2, B2);
    k_wproj<<<32768, 256>>>(W3_win, b3_win, W3_wout, b3_wout);
    k_small<<<512,   128>>>(W3_b, b3_b, W3_gate, b3_gate);
    k_tc   <<<Bd / TMr, 256, SMEM_TC>>>(zlp, out);
}